// round 1
// baseline (speedup 1.0000x reference)
#include <cuda_runtime.h>

#define CIN 256
#define SQRT2F 1.41421356237309515f
#define INV_SQRT2F 0.70710678118654752f

// ---------------- scratch (device globals: no cudaMalloc allowed) ----------------
__device__ float g_tmp1[8u * 256u * 64u * 64u];      // conv1 output (post-act), 33.5 MB
__device__ float g_up  [8u * 256u * 128u * 128u];    // upsampled conv1 output, 134 MB
__device__ float g_skip[8u * 128u * 64u * 64u];      // 1x1 skip conv at 64x64, 16.8 MB
__device__ float g_w1t [256u * 9u * 256u];           // w1 transposed [ci][tap][co], scaled
__device__ float g_w2t [256u * 9u * 128u];           // w2 transposed
__device__ float g_wskt[256u * 128u];                // w_skip transposed [ci][co], scaled

// bilinear 2x upsample taps (half-pixel centers, edge clamp) — matches
// jax.image.resize / torch interpolate(align_corners=False)
__device__ __forceinline__ void up_taps(int o, int lim, int& a, int& b, float& fa, float& fb)
{
    int i = o >> 1;
    if (o & 1) { a = i;               b = (i + 1 < lim) ? i + 1 : lim; fa = 0.75f; fb = 0.25f; }
    else       { a = (i - 1 > 0) ? i - 1 : 0; b = i;                   fa = 0.25f; fb = 0.75f; }
}

// ---------------- weight prep ----------------
// w: [COUT][256][3][3] (OIHW) -> wt: [(ci*9+tap)*COUT + co], scaled
__global__ void transpose_w3_kernel(const float* __restrict__ w, float* __restrict__ wt,
                                    int cout, float scale)
{
    int idx = blockIdx.x * 256 + threadIdx.x;
    int total = cout * 2304;
    if (idx >= total) return;
    int co  = idx / 2304;
    int rem = idx - co * 2304;
    int ci  = rem / 9;
    int tap = rem - ci * 9;
    wt[(ci * 9 + tap) * cout + co] = w[idx] * scale;
}

// w: [128][256] -> wt: [ci*128 + co], scaled
__global__ void transpose_w1x1_kernel(const float* __restrict__ w, float* __restrict__ wt,
                                      float scale)
{
    int idx = blockIdx.x * 256 + threadIdx.x;   // 32768 total, exact
    int co = idx >> 8;
    int ci = idx & 255;
    wt[ci * 128 + co] = w[idx] * scale;
}

// ---------------- skip path: 1x1 conv at 64x64 ----------------
// block: 64 px x 128 co, 256 threads, each thread 8 co x 4 px
__global__ __launch_bounds__(256, 2)
void skip1x1_kernel(const float* __restrict__ x, const float* __restrict__ wt,
                    float* __restrict__ dst)
{
    __shared__ float Xs[16][64];
    __shared__ float Wh[16][128];

    const int n      = blockIdx.y;
    const int pxBase = blockIdx.x * 64;
    const int tid    = threadIdx.x;
    const int cog    = tid & 15;   // 16 groups x 8 co
    const int pxg    = tid >> 4;   // 16 groups x 4 px

    float acc[8][4];
#pragma unroll
    for (int j = 0; j < 8; j++)
#pragma unroll
        for (int p = 0; p < 4; p++) acc[j][p] = 0.f;

    const float* xN = x + (size_t)n * CIN * 4096;

    for (int ciB = 0; ciB < CIN; ciB += 16) {
        for (int idx = tid; idx < 1024; idx += 256) {
            int ci = idx >> 6, px = idx & 63;
            Xs[ci][px] = xN[(size_t)(ciB + ci) * 4096 + pxBase + px];
        }
        for (int idx = tid; idx < 2048; idx += 256) {
            int ci = idx >> 7, co = idx & 127;
            Wh[ci][co] = wt[(ciB + ci) * 128 + co];
        }
        __syncthreads();

#pragma unroll 4
        for (int ci = 0; ci < 16; ci++) {
            const float4 xv = *reinterpret_cast<const float4*>(&Xs[ci][pxg * 4]);
            const float4 w0 = *reinterpret_cast<const float4*>(&Wh[ci][cog * 8]);
            const float4 w1 = *reinterpret_cast<const float4*>(&Wh[ci][cog * 8 + 4]);
            float wv[8] = {w0.x, w0.y, w0.z, w0.w, w1.x, w1.y, w1.z, w1.w};
            float xs[4] = {xv.x, xv.y, xv.z, xv.w};
#pragma unroll
            for (int j = 0; j < 8; j++)
#pragma unroll
                for (int p = 0; p < 4; p++)
                    acc[j][p] = fmaf(wv[j], xs[p], acc[j][p]);
        }
        __syncthreads();
    }

#pragma unroll
    for (int j = 0; j < 8; j++) {
        int co = cog * 8 + j;
#pragma unroll
        for (int p = 0; p < 4; p++)
            dst[((size_t)n * 128 + co) * 4096 + pxBase + pxg * 4 + p] = acc[j][p];
    }
}

// ---------------- bilinear 2x upsample: [8*256][64][64] -> [8*256][128][128] ----------------
__global__ void upsample2x_kernel(const float* __restrict__ src, float* __restrict__ dst)
{
    int idx = blockIdx.x * 256 + threadIdx.x;     // 33554432 total, exact
    int c   = idx >> 14;
    int rem = idx & 16383;
    int oh  = rem >> 7;
    int ow  = rem & 127;
    int ha, hb, wa, wb; float fha, fhb, fwa, fwb;
    up_taps(oh, 63, ha, hb, fha, fhb);
    up_taps(ow, 63, wa, wb, fwa, fwb);
    const float* S = src + (size_t)c * 4096;
    dst[idx] = fha * (fwa * S[ha * 64 + wa] + fwb * S[ha * 64 + wb]) +
               fhb * (fwa * S[hb * 64 + wa] + fwb * S[hb * 64 + wb]);
}

// ---------------- 3x3 conv (pad=1) + bias + FusedLeakyReLU [+ skip add] ----------------
// block tile: 64 couts x (8 rows x 16 cols) pixels, 256 threads,
// each thread: 8 contiguous couts x 4 contiguous cols.
template <int HH, int WW, int COUT, bool FUSE>
__global__ __launch_bounds__(256, 2)
void conv3x3_kernel(const float* __restrict__ in, const float* __restrict__ wt,
                    const float* __restrict__ bias, const float* __restrict__ skipsrc,
                    float* __restrict__ outp)
{
    __shared__ float Xs[8][10][20];   // ci, row(+halo), col(+halo, padded)
    __shared__ float Ws[8][9][64];    // ci, tap, co

    const int n      = blockIdx.z;
    const int coBase = blockIdx.y * 64;
    const int ntx    = WW / 16;
    const int tx     = blockIdx.x % ntx;
    const int ty     = blockIdx.x / ntx;
    const int bx0    = tx * 16;
    const int by0    = ty * 8;
    const int tid    = threadIdx.x;
    const int cog    = tid & 7;           // 8 groups x 8 co
    const int pxg    = tid >> 3;          // 32 groups x 4 px
    const int r      = pxg >> 2;          // row within tile
    const int c0     = (pxg & 3) * 4;     // col group base

    float acc[8][4];
#pragma unroll
    for (int j = 0; j < 8; j++)
#pragma unroll
        for (int p = 0; p < 4; p++) acc[j][p] = 0.f;

    const float* inN = in + (size_t)n * CIN * HH * WW;

    for (int ciB = 0; ciB < CIN; ciB += 8) {
        // stage input halo tile
        for (int idx = tid; idx < 8 * 10 * 18; idx += 256) {
            int ci  = idx / 180;
            int rem = idx - ci * 180;
            int row = rem / 18;
            int col = rem - row * 18;
            int gy  = by0 + row - 1;
            int gx  = bx0 + col - 1;
            float v = 0.f;
            if ((unsigned)gy < (unsigned)HH && (unsigned)gx < (unsigned)WW)
                v = inN[(size_t)(ciB + ci) * HH * WW + gy * WW + gx];
            Xs[ci][row][col] = v;
        }
        // stage weights (pre-transposed: co contiguous -> coalesced)
        for (int idx = tid; idx < 8 * 9 * 64; idx += 256) {
            int ci  = idx / 576;
            int rem = idx - ci * 576;
            int tap = rem >> 6;
            int co  = rem & 63;
            Ws[ci][tap][co] = wt[((ciB + ci) * 9 + tap) * COUT + coBase + co];
        }
        __syncthreads();

#pragma unroll 2
        for (int ci = 0; ci < 8; ci++) {
            float xr[3][6];
#pragma unroll
            for (int dy = 0; dy < 3; dy++)
#pragma unroll
                for (int k = 0; k < 6; k++)
                    xr[dy][k] = Xs[ci][r + dy][c0 + k];
#pragma unroll
            for (int ky = 0; ky < 3; ky++)
#pragma unroll
                for (int kx = 0; kx < 3; kx++) {
                    const float4 wa = *reinterpret_cast<const float4*>(&Ws[ci][ky * 3 + kx][cog * 8]);
                    const float4 wb = *reinterpret_cast<const float4*>(&Ws[ci][ky * 3 + kx][cog * 8 + 4]);
                    float wv[8] = {wa.x, wa.y, wa.z, wa.w, wb.x, wb.y, wb.z, wb.w};
#pragma unroll
                    for (int p = 0; p < 4; p++) {
                        float xv = xr[ky][p + kx];
#pragma unroll
                        for (int j = 0; j < 8; j++)
                            acc[j][p] = fmaf(wv[j], xv, acc[j][p]);
                    }
                }
        }
        __syncthreads();
    }

    // epilogue
    const int gy = by0 + r;
    int ha = 0, hb = 0; float fha = 0.f, fhb = 0.f;
    int wa4[4], wb4[4]; float fwa4[4], fwb4[4];
    if (FUSE) {
        up_taps(gy, 63, ha, hb, fha, fhb);
#pragma unroll
        for (int p = 0; p < 4; p++)
            up_taps(bx0 + c0 + p, 63, wa4[p], wb4[p], fwa4[p], fwb4[p]);
    }

#pragma unroll
    for (int j = 0; j < 8; j++) {
        const int co = coBase + cog * 8 + j;
        const float b = __ldg(&bias[co]);
#pragma unroll
        for (int p = 0; p < 4; p++) {
            const int gx = bx0 + c0 + p;
            float v = acc[j][p] + b;
            v *= (v >= 0.f) ? SQRT2F : (0.2f * SQRT2F);   // leaky(0.2) * sqrt(2)
            if (!FUSE) {
                outp[((size_t)(n * COUT + co) * HH + gy) * WW + gx] = v;
            } else {
                const float* S = skipsrc + ((size_t)n * 128 + co) * 4096;
                float sk = fha * (fwa4[p] * S[ha * 64 + wa4[p]] + fwb4[p] * S[ha * 64 + wb4[p]]) +
                           fhb * (fwa4[p] * S[hb * 64 + wa4[p]] + fwb4[p] * S[hb * 64 + wb4[p]]);
                outp[((size_t)(n * COUT + co) * HH + gy) * WW + gx] = (v + sk) * INV_SQRT2F;
            }
        }
    }
}

// ---------------- launch ----------------
extern "C" void kernel_launch(void* const* d_in, const int* in_sizes, int n_in,
                              void* d_out, int out_size)
{
    const float* x   = (const float*)d_in[0];
    const float* w1  = (const float*)d_in[1];
    const float* b1  = (const float*)d_in[2];
    const float* w2  = (const float*)d_in[3];
    const float* b2  = (const float*)d_in[4];
    const float* wsk = (const float*)d_in[5];
    float* out = (float*)d_out;

    void *p_tmp1, *p_up, *p_skip, *p_w1t, *p_w2t, *p_wskt;
    cudaGetSymbolAddress(&p_tmp1, g_tmp1);
    cudaGetSymbolAddress(&p_up,   g_up);
    cudaGetSymbolAddress(&p_skip, g_skip);
    cudaGetSymbolAddress(&p_w1t,  g_w1t);
    cudaGetSymbolAddress(&p_w2t,  g_w2t);
    cudaGetSymbolAddress(&p_wskt, g_wskt);
    float* tmp1 = (float*)p_tmp1;
    float* up   = (float*)p_up;
    float* skip = (float*)p_skip;
    float* w1t  = (float*)p_w1t;
    float* w2t  = (float*)p_w2t;
    float* wskt = (float*)p_wskt;

    const float scale3 = 1.0f / 48.0f;   // 1/sqrt(256*9)
    const float scale1 = 1.0f / 16.0f;   // 1/sqrt(256)

    // weight prep (fold equalized-lr scales, transpose for coalesced staging)
    transpose_w3_kernel<<<2304, 256>>>(w1, w1t, 256, scale3);
    transpose_w3_kernel<<<1152, 256>>>(w2, w2t, 128, scale3);
    transpose_w1x1_kernel<<<128, 256>>>(wsk, wskt, scale1);

    // skip path at 64x64 (upsample commutes with 1x1 conv -> 4x fewer FLOPs)
    skip1x1_kernel<<<dim3(64, 8), 256>>>(x, wskt, skip);

    // conv1 + FusedLeakyReLU at 64x64
    conv3x3_kernel<64, 64, 256, false><<<dim3(32, 4, 8), 256>>>(x, w1t, b1, nullptr, tmp1);

    // bilinear 2x upsample of activated conv1 output
    upsample2x_kernel<<<131072, 256>>>(tmp1, up);

    // conv2 + FusedLeakyReLU at 128x128, fused with skip bilinear-add and /sqrt(2)
    conv3x3_kernel<128, 128, 128, true><<<dim3(128, 2, 8), 256>>>(up, w2t, b2, skip, out);
}

// round 3
// speedup vs baseline: 2.9257x; 2.9257x over previous
#include <cuda_runtime.h>
#include <cstdint>

#define CIN 256
#define SQRT2F 1.41421356237309515f
#define INV_SQRT2F 0.70710678118654752f

// ---------------- scratch (device globals: no cudaMalloc allowed) ----------------
__device__ float g_tmp1  [8u * 256u * 64u * 64u];     // conv1 output (post-act)
__device__ float g_up    [8u * 256u * 128u * 128u];   // upsampled conv1 output
__device__ float g_skip  [8u * 128u * 64u * 64u];     // 1x1 skip at 64x64
__device__ float g_skipup[8u * 128u * 128u * 128u];   // upsampled skip at 128x128
__device__ float g_w1t [256u * 9u * 256u];            // [ci][tap][co], tf32, scaled
__device__ float g_w2t [256u * 9u * 128u];
__device__ float g_wskt[256u * 128u];

// round fp32 -> tf32 (rna) keeping it in a b32/f32 register
__device__ __forceinline__ uint32_t f2tf32(float x)
{
    uint32_t u;
    asm("cvt.rna.tf32.f32 %0, %1;" : "=r"(u) : "f"(x));
    return u;
}

__device__ __forceinline__ void mma_tf32(float* c, const uint32_t* a, const uint32_t* b)
{
    asm volatile(
        "mma.sync.aligned.m16n8k8.row.col.f32.tf32.tf32.f32 "
        "{%0,%1,%2,%3}, {%4,%5,%6,%7}, {%8,%9}, {%0,%1,%2,%3};"
        : "+f"(c[0]), "+f"(c[1]), "+f"(c[2]), "+f"(c[3])
        : "r"(a[0]), "r"(a[1]), "r"(a[2]), "r"(a[3]), "r"(b[0]), "r"(b[1]));
}

// bilinear 2x upsample taps (half-pixel centers, edge clamp)
__device__ __forceinline__ void up_taps(int o, int lim, int& a, int& b, float& fa, float& fb)
{
    int i = o >> 1;
    if (o & 1) { a = i;                    b = (i + 1 < lim) ? i + 1 : lim; fa = 0.75f; fb = 0.25f; }
    else       { a = (i - 1 > 0) ? i - 1 : 0; b = i;                        fa = 0.25f; fb = 0.75f; }
}

// smallest pad >= cw with (xr*pad) % 32 == 8  (makes fragment LDS conflict-free)
__host__ __device__ constexpr int cpad_calc(int xr, int cw)
{
    int p = cw;
    while ((xr * p) % 32 != 8) p++;
    return p;
}

// ---------------- weight prep: OIHW -> [ci][tap][co], tf32-rounded, scaled ----------------
__global__ void transpose_w3_kernel(const float* __restrict__ w, float* __restrict__ wt,
                                    int cout, float scale)
{
    int idx = blockIdx.x * 256 + threadIdx.x;
    if (idx >= cout * 2304) return;
    int co  = idx / 2304;
    int rem = idx - co * 2304;
    int ci  = rem / 9;
    int tap = rem - ci * 9;
    wt[((size_t)ci * 9 + tap) * cout + co] = __uint_as_float(f2tf32(w[idx] * scale));
}

__global__ void transpose_w1x1_kernel(const float* __restrict__ w, float* __restrict__ wt,
                                      float scale)
{
    int idx = blockIdx.x * 256 + threadIdx.x;   // 32768 exact
    int co = idx >> 8;
    int ci = idx & 255;
    wt[ci * 128 + co] = __uint_as_float(f2tf32(w[idx] * scale));
}

// ---------------- bilinear 2x upsample ----------------
__global__ void upsample2x_kernel(const float* __restrict__ src, float* __restrict__ dst,
                                  int total)
{
    int idx = blockIdx.x * 256 + threadIdx.x;
    if (idx >= total) return;
    int c   = idx >> 14;
    int rem = idx & 16383;
    int oh  = rem >> 7;
    int ow  = rem & 127;
    int ha, hb, wa, wb; float fha, fhb, fwa, fwb;
    up_taps(oh, 63, ha, hb, fha, fhb);
    up_taps(ow, 63, wa, wb, fwa, fwb);
    const float* S = src + (size_t)c * 4096;
    dst[idx] = fha * (fwa * S[ha * 64 + wa] + fwb * S[ha * 64 + wb]) +
               fhb * (fwa * S[hb * 64 + wa] + fwb * S[hb * 64 + wb]);
}

// ---------------- tf32 tensor-core implicit-GEMM conv ----------------
// Block: 256 thr (8 warps). Output tile: 128 px x 128 co.
// Warp tile: 64 px x 32 co = 4 m-frags x 4 n-frags of m16n8k8.
// K loop: ci in chunks of 8 (one k-step per tap per chunk).
// px tile geometry: NROWS rows x TW cols (NROWS*TW == 128).
template <int NROWS, int TW, int H, int KS, int COUT, bool ACT, bool FUSE>
__global__ __launch_bounds__(256, 2)
void conv_mma_kernel(const float* __restrict__ in, const float* __restrict__ wt,
                     const float* __restrict__ bias, const float* __restrict__ skipup,
                     float* __restrict__ outp)
{
    constexpr int KS2  = KS * KS;
    constexpr int XR   = NROWS + KS - 1;            // staged input rows
    constexpr int CW   = TW + (KS == 3 ? 2 : 0);    // staged input cols
    constexpr int CPAD = cpad_calc(XR, CW);         // per-row stride (banks)
    constexpr int XRC  = XR * CPAD;                 // per-ci stride, == 8 mod 32
    constexpr int WST  = 136;                       // per-ci weight stride, == 8 mod 32

    extern __shared__ float smem[];
    float* Ws = smem;                    // [KS2][8][WST]
    float* Xs = smem + KS2 * 8 * WST;    // [8][XR][CPAD]

    const int tid   = threadIdx.x;
    const int lane  = tid & 31;
    const int warp  = tid >> 5;
    const int g     = lane >> 2;     // 0..7
    const int t     = lane & 3;      // 0..3
    const int warpM = warp & 1;      // px half (64 px)
    const int warpN = warp >> 1;     // co quarter (32 co)

    const int n       = blockIdx.z;
    const int coBase  = blockIdx.y * 128;
    const int rowBase = blockIdx.x * NROWS;

    const float* inN = in + (size_t)n * CIN * H * TW;

    float acc[4][4][4];
#pragma unroll
    for (int i = 0; i < 4; i++)
#pragma unroll
        for (int j = 0; j < 4; j++)
#pragma unroll
            for (int k = 0; k < 4; k++) acc[i][j][k] = 0.f;

    const int r0 = (TW == 64) ? warpM : 0;  // local row of this warp's px tile

    for (int ciB = 0; ciB < CIN; ciB += 8) {
        // ---- stage input halo tile (tf32-rounded) ----
#pragma unroll 4
        for (int idx = tid; idx < 8 * XR * CW; idx += 256) {
            int ci  = idx / (XR * CW);
            int rem = idx - ci * (XR * CW);
            int rr  = rem / CW;
            int cc  = rem - rr * CW;
            int gy  = rowBase + rr - (KS == 3 ? 1 : 0);
            int gx  = cc - (KS == 3 ? 1 : 0);
            float v = 0.f;
            if ((unsigned)gy < (unsigned)H && (unsigned)gx < (unsigned)TW)
                v = inN[(size_t)(ciB + ci) * H * TW + gy * TW + gx];
            Xs[ci * XRC + rr * CPAD + cc] = __uint_as_float(f2tf32(v));
        }
        // ---- stage weights [tap][ci][co] (pre-rounded) ----
#pragma unroll 4
        for (int idx = tid; idx < KS2 * 8 * 128; idx += 256) {
            int co  = idx & 127;
            int ci  = (idx >> 7) & 7;
            int tap = idx >> 10;
            Ws[(tap * 8 + ci) * WST + co] =
                wt[((size_t)(ciB + ci) * KS2 + tap) * COUT + coBase + co];
        }
        __syncthreads();

        // ---- compute: KS2 taps x 16 mma ----
#pragma unroll
        for (int ky = 0; ky < KS; ky++)
#pragma unroll
            for (int kx = 0; kx < KS; kx++) {
                const int tap = ky * KS + kx;
                uint32_t a[4][4], b[4][2];
#pragma unroll
                for (int mf = 0; mf < 4; mf++) {
                    const int cb = ((TW == 64) ? 0 : warpM * 64) + mf * 16 + g;
                    const float* p = &Xs[(r0 + ky) * CPAD + cb + kx];
                    a[mf][0] = __float_as_uint(p[t * XRC]);
                    a[mf][1] = __float_as_uint(p[t * XRC + 8]);
                    a[mf][2] = __float_as_uint(p[(t + 4) * XRC]);
                    a[mf][3] = __float_as_uint(p[(t + 4) * XRC + 8]);
                }
#pragma unroll
                for (int nf = 0; nf < 4; nf++) {
                    const int co = warpN * 32 + nf * 8 + g;
                    b[nf][0] = __float_as_uint(Ws[(tap * 8 + t) * WST + co]);
                    b[nf][1] = __float_as_uint(Ws[(tap * 8 + t + 4) * WST + co]);
                }
#pragma unroll
                for (int mf = 0; mf < 4; mf++)
#pragma unroll
                    for (int nf = 0; nf < 4; nf++)
                        mma_tf32(acc[mf][nf], a[mf], b[nf]);
            }
        __syncthreads();
    }

    // ---- epilogue: bias + leaky*sqrt2 [+ skip add] ----
    const int gy = rowBase + r0;
#pragma unroll
    for (int nf = 0; nf < 4; nf++) {
#pragma unroll
        for (int q = 0; q < 2; q++) {
            const int co = coBase + warpN * 32 + nf * 8 + t * 2 + q;
            const float bv = ACT ? __ldg(&bias[co]) : 0.f;
#pragma unroll
            for (int mf = 0; mf < 4; mf++) {
                const int cb = ((TW == 64) ? 0 : warpM * 64) + mf * 16 + g;
#pragma unroll
                for (int h = 0; h < 2; h++) {
                    float v = acc[mf][nf][h * 2 + q] + bv;
                    if (ACT) v *= (v >= 0.f) ? SQRT2F : (0.2f * SQRT2F);
                    size_t oidx = (((size_t)n * COUT + co) * H + gy) * TW + cb + h * 8;
                    if (FUSE) v = (v + skipup[oidx]) * INV_SQRT2F;
                    outp[oidx] = v;
                }
            }
        }
    }
}

// ---------------- launch ----------------
extern "C" void kernel_launch(void* const* d_in, const int* in_sizes, int n_in,
                              void* d_out, int out_size)
{
    const float* x   = (const float*)d_in[0];
    const float* w1  = (const float*)d_in[1];
    const float* b1  = (const float*)d_in[2];
    const float* w2  = (const float*)d_in[3];
    const float* b2  = (const float*)d_in[4];
    const float* wsk = (const float*)d_in[5];
    float* out = (float*)d_out;

    void *p0, *p1, *p2, *p3, *p4, *p5, *p6;
    cudaGetSymbolAddress(&p0, g_tmp1);
    cudaGetSymbolAddress(&p1, g_up);
    cudaGetSymbolAddress(&p2, g_skip);
    cudaGetSymbolAddress(&p3, g_skipup);
    cudaGetSymbolAddress(&p4, g_w1t);
    cudaGetSymbolAddress(&p5, g_w2t);
    cudaGetSymbolAddress(&p6, g_wskt);
    float* tmp1   = (float*)p0;
    float* up     = (float*)p1;
    float* skip   = (float*)p2;
    float* skipup = (float*)p3;
    float* w1t    = (float*)p4;
    float* w2t    = (float*)p5;
    float* wskt   = (float*)p6;

    const float scale3 = 1.0f / 48.0f;   // 1/sqrt(256*9)
    const float scale1 = 1.0f / 16.0f;   // 1/sqrt(256)

    // kernel pointers + smem sizes
    auto kconv1 = conv_mma_kernel<2, 64, 64, 3, 256, true, false>;
    auto kconv2 = conv_mma_kernel<1, 128, 128, 3, 128, true, true>;
    auto kskip  = conv_mma_kernel<2, 64, 64, 1, 128, false, false>;

    constexpr int SM_C1 = (9 * 8 * 136 + 8 * 4 * cpad_calc(4, 66))  * 4;  // 47616
    constexpr int SM_C2 = (9 * 8 * 136 + 8 * 3 * cpad_calc(3, 130)) * 4;  // 53760
    constexpr int SM_SK = (1 * 8 * 136 + 8 * 2 * cpad_calc(2, 64))  * 4;  //  8704

    cudaFuncSetAttribute(kconv1, cudaFuncAttributeMaxDynamicSharedMemorySize, SM_C1);
    cudaFuncSetAttribute(kconv2, cudaFuncAttributeMaxDynamicSharedMemorySize, SM_C2);
    cudaFuncSetAttribute(kskip,  cudaFuncAttributeMaxDynamicSharedMemorySize, SM_SK);

    // weight prep (tf32 rounding + equalized-lr scale + transpose)
    transpose_w3_kernel<<<2304, 256>>>(w1, w1t, 256, scale3);
    transpose_w3_kernel<<<1152, 256>>>(w2, w2t, 128, scale3);
    transpose_w1x1_kernel<<<128, 256>>>(wsk, wskt, scale1);

    // skip: 1x1 conv at 64x64 (commuted past upsample), then upsample to 128^2
    kskip<<<dim3(32, 1, 8), 256, SM_SK>>>(x, wskt, nullptr, nullptr, skip);
    upsample2x_kernel<<<65536, 256>>>(skip, skipup, 8 * 128 * 128 * 128);

    // conv1 + FusedLeakyReLU at 64x64
    kconv1<<<dim3(32, 2, 8), 256, SM_C1>>>(x, w1t, b1, nullptr, tmp1);

    // bilinear 2x upsample of activated conv1 output
    upsample2x_kernel<<<131072, 256>>>(tmp1, up, 8 * 256 * 128 * 128);

    // conv2 + FusedLeakyReLU at 128^2, fused skip add + /sqrt(2)
    kconv2<<<dim3(128, 1, 8), 256, SM_C2>>>(up, w2t, b2, skipup, out);
}

// round 4
// speedup vs baseline: 5.4848x; 1.8747x over previous
#include <cuda_runtime.h>
#include <cstdint>

#define CIN 256
#define SQRT2F 1.41421356237309515f
#define INV_SQRT2F 0.70710678118654752f

// ---------------- scratch (device globals: no cudaMalloc allowed) ----------------
__device__ float g_xr    [8u * 256u * 64u * 64u];     // tf32-rounded x
__device__ float g_tmp1  [8u * 256u * 64u * 64u];     // conv1 output (post-act, fp32)
__device__ float g_up    [8u * 256u * 128u * 128u];   // upsampled conv1 out (tf32-rounded)
__device__ float g_skip  [8u * 128u * 64u * 64u];     // 1x1 skip at 64x64 (fp32)
__device__ float g_skipup[8u * 128u * 128u * 128u];   // upsampled skip at 128x128 (fp32)
__device__ float g_w1t [256u * 9u * 256u];            // [ci][tap][co], tf32, scaled
__device__ float g_w2t [256u * 9u * 128u];
__device__ float g_wskt[256u * 128u];

// ---------------- small helpers ----------------
__device__ __forceinline__ uint32_t f2tf32(float x)
{
    uint32_t u;
    asm("cvt.rna.tf32.f32 %0, %1;" : "=r"(u) : "f"(x));
    return u;
}

__device__ __forceinline__ void mma_tf32(float* c, const uint32_t* a, const uint32_t* b)
{
    asm volatile(
        "mma.sync.aligned.m16n8k8.row.col.f32.tf32.tf32.f32 "
        "{%0,%1,%2,%3}, {%4,%5,%6,%7}, {%8,%9}, {%0,%1,%2,%3};"
        : "+f"(c[0]), "+f"(c[1]), "+f"(c[2]), "+f"(c[3])
        : "r"(a[0]), "r"(a[1]), "r"(a[2]), "r"(a[3]), "r"(b[0]), "r"(b[1]));
}

__device__ __forceinline__ void cp_async4_z(float* dst, const float* src, bool ok)
{
    uint32_t d = (uint32_t)__cvta_generic_to_shared(dst);
    int sz = ok ? 4 : 0;     // src-size 0 -> zero fill (halo)
    asm volatile("cp.async.ca.shared.global [%0], [%1], 4, %2;" :: "r"(d), "l"(src), "r"(sz));
}
__device__ __forceinline__ void cp_async16(float* dst, const float* src)
{
    uint32_t d = (uint32_t)__cvta_generic_to_shared(dst);
    asm volatile("cp.async.cg.shared.global [%0], [%1], 16;" :: "r"(d), "l"(src));
}
__device__ __forceinline__ void cp_commit() { asm volatile("cp.async.commit_group;"); }
template <int N>
__device__ __forceinline__ void cp_wait() { asm volatile("cp.async.wait_group %0;" :: "n"(N)); }

// bilinear 2x upsample taps (half-pixel centers, edge clamp)
__device__ __forceinline__ void up_taps(int o, int lim, int& a, int& b, float& fa, float& fb)
{
    int i = o >> 1;
    if (o & 1) { a = i;                    b = (i + 1 < lim) ? i + 1 : lim; fa = 0.75f; fb = 0.25f; }
    else       { a = (i - 1 > 0) ? i - 1 : 0; b = i;                        fa = 0.25f; fb = 0.75f; }
}

// smallest pad >= cw with (xr*pad) % 32 == 8  (conflict-free fragment LDS)
__host__ __device__ constexpr int cpad_calc(int xr, int cw)
{
    int p = cw;
    while ((xr * p) % 32 != 8) p++;
    return p;
}

// ---------------- prep kernels ----------------
__global__ void round_tf32_kernel(const float* __restrict__ src, float* __restrict__ dst,
                                  int total)
{
    int i = blockIdx.x * 256 + threadIdx.x;
    if (i < total) dst[i] = __uint_as_float(f2tf32(src[i]));
}

__global__ void transpose_w3_kernel(const float* __restrict__ w, float* __restrict__ wt,
                                    int cout, float scale)
{
    int idx = blockIdx.x * 256 + threadIdx.x;
    if (idx >= cout * 2304) return;
    int co  = idx / 2304;
    int rem = idx - co * 2304;
    int ci  = rem / 9;
    int tap = rem - ci * 9;
    wt[((size_t)ci * 9 + tap) * cout + co] = __uint_as_float(f2tf32(w[idx] * scale));
}

__global__ void transpose_w1x1_kernel(const float* __restrict__ w, float* __restrict__ wt,
                                      float scale)
{
    int idx = blockIdx.x * 256 + threadIdx.x;   // 32768 exact
    int co = idx >> 8;
    int ci = idx & 255;
    wt[ci * 128 + co] = __uint_as_float(f2tf32(w[idx] * scale));
}

template <bool ROUND>
__global__ void upsample2x_kernel(const float* __restrict__ src, float* __restrict__ dst,
                                  int total)
{
    int idx = blockIdx.x * 256 + threadIdx.x;
    if (idx >= total) return;
    int c   = idx >> 14;
    int rem = idx & 16383;
    int oh  = rem >> 7;
    int ow  = rem & 127;
    int ha, hb, wa, wb; float fha, fhb, fwa, fwb;
    up_taps(oh, 63, ha, hb, fha, fhb);
    up_taps(ow, 63, wa, wb, fwa, fwb);
    const float* S = src + (size_t)c * 4096;
    float v = fha * (fwa * S[ha * 64 + wa] + fwb * S[ha * 64 + wb]) +
              fhb * (fwa * S[hb * 64 + wa] + fwb * S[hb * 64 + wb]);
    dst[idx] = ROUND ? __uint_as_float(f2tf32(v)) : v;
}

// ---------------- tf32 tensor-core implicit-GEMM conv, cp.async 2-stage pipeline ----
// Block: 256 thr (8 warps). Output tile: 128 px (TH rows x 64 cols) x 128 co.
// Warp tile: 64 px x 32 co = 4 m-frags x 4 n-frags of m16n8k8.
template <int TH, int H, int W, int KS, int COUT, bool ACT, bool FUSE>
__global__ __launch_bounds__(256, 2)
void conv_mma_kernel(const float* __restrict__ in, const float* __restrict__ wt,
                     const float* __restrict__ bias, const float* __restrict__ skipup,
                     float* __restrict__ outp)
{
    constexpr int KS2   = KS * KS;
    constexpr int PAD   = (KS == 3) ? 1 : 0;
    constexpr int TWID  = 64;
    constexpr int XR    = TH + KS - 1;
    constexpr int CW    = TWID + 2 * PAD;
    constexpr int CPAD  = cpad_calc(XR, CW);
    constexpr int XRC   = XR * CPAD;          // per-ci stride, == 8 mod 32
    constexpr int WST   = 136;                // per-(tap,ci) stride, == 8 mod 32
    constexpr int WSTG  = KS2 * 8 * WST;
    constexpr int XSTG  = 8 * XRC;
    constexpr int STAGE = WSTG + XSTG;
    constexpr int NCH   = CIN / 8;

    extern __shared__ float smem[];

    const int tid   = threadIdx.x;
    const int lane  = tid & 31;
    const int warp  = tid >> 5;
    const int g     = lane >> 2;
    const int t     = lane & 3;
    const int warpM = warp & 1;     // row within px tile
    const int warpN = warp >> 1;    // co quarter (32 co)

    const int n       = blockIdx.z;
    const int coBase  = blockIdx.y * 128;
    constexpr int tilesX = W / TWID;
    const int colBase = (blockIdx.x % tilesX) * TWID;
    const int rowBase = (blockIdx.x / tilesX) * TH;

    const float* inN = in + (size_t)n * CIN * H * W;

    // ---- staging (cp.async) ----
    auto stage = [&](int chunk) {
        float* base = smem + (chunk & 1) * STAGE;
        float* Wsb  = base;
        float* Xsb  = base + WSTG;
        const int ciB = chunk * 8;
        // weights: 16B vectors, fully coalesced
#pragma unroll
        for (int idx = tid; idx < KS2 * 8 * 32; idx += 256) {
            int q   = idx & 31;
            int ci  = (idx >> 5) & 7;
            int tap = idx >> 8;
            cp_async16(&Wsb[(tap * 8 + ci) * WST + q * 4],
                       &wt[((size_t)(ciB + ci) * KS2 + tap) * COUT + coBase + q * 4]);
        }
        // input halo tile: 4B with zero-fill at borders
#pragma unroll
        for (int idx = tid; idx < 8 * XR * CW; idx += 256) {
            int ci  = idx / (XR * CW);
            int rem = idx - ci * (XR * CW);
            int rr  = rem / CW;
            int cc  = rem - rr * CW;
            int gy  = rowBase + rr - PAD;
            int gx  = colBase + cc - PAD;
            bool ok = ((unsigned)gy < (unsigned)H) && ((unsigned)gx < (unsigned)W);
            const float* src = ok ? &inN[(size_t)(ciB + ci) * H * W + gy * W + gx] : inN;
            cp_async4_z(&Xsb[ci * XRC + rr * CPAD + cc], src, ok);
        }
    };

    float acc[4][4][4];
#pragma unroll
    for (int i = 0; i < 4; i++)
#pragma unroll
        for (int j = 0; j < 4; j++)
#pragma unroll
            for (int k = 0; k < 4; k++) acc[i][j][k] = 0.f;

    stage(0); cp_commit();
    stage(1); cp_commit();

    for (int c = 0; c < NCH; c++) {
        if (c + 1 < NCH) cp_wait<1>(); else cp_wait<0>();
        __syncthreads();

        const float* base = smem + (c & 1) * STAGE;
        const float* Wsb  = base;
        const float* Xsb  = base + WSTG;

#pragma unroll
        for (int ky = 0; ky < KS; ky++)
#pragma unroll
            for (int kx = 0; kx < KS; kx++) {
                const int tap = ky * KS + kx;
                uint32_t a[4][4], b[4][2];
#pragma unroll
                for (int mf = 0; mf < 4; mf++) {
                    const int cb = mf * 16 + g;
                    const float* p = &Xsb[(warpM + ky) * CPAD + cb + kx];
                    a[mf][0] = __float_as_uint(p[t * XRC]);
                    a[mf][1] = __float_as_uint(p[t * XRC + 8]);
                    a[mf][2] = __float_as_uint(p[(t + 4) * XRC]);
                    a[mf][3] = __float_as_uint(p[(t + 4) * XRC + 8]);
                }
#pragma unroll
                for (int nf = 0; nf < 4; nf++) {
                    const int co = warpN * 32 + nf * 8 + g;
                    b[nf][0] = __float_as_uint(Wsb[(tap * 8 + t) * WST + co]);
                    b[nf][1] = __float_as_uint(Wsb[(tap * 8 + t + 4) * WST + co]);
                }
#pragma unroll
                for (int mf = 0; mf < 4; mf++)
#pragma unroll
                    for (int nf = 0; nf < 4; nf++)
                        mma_tf32(acc[mf][nf], a[mf], b[nf]);
            }
        __syncthreads();

        if (c + 2 < NCH) { stage(c + 2); cp_commit(); }
    }

    // ---- epilogue: bias + leaky*sqrt2 [+ skip add, /sqrt2] ----
    const int gy = rowBase + warpM;
#pragma unroll
    for (int nf = 0; nf < 4; nf++) {
#pragma unroll
        for (int q = 0; q < 2; q++) {
            const int co = coBase + warpN * 32 + nf * 8 + t * 2 + q;
            const float bv = ACT ? __ldg(&bias[co]) : 0.f;
#pragma unroll
            for (int mf = 0; mf < 4; mf++) {
                const int cb = mf * 16 + g;
#pragma unroll
                for (int h = 0; h < 2; h++) {
                    float v = acc[mf][nf][h * 2 + q] + bv;
                    if (ACT) v *= (v >= 0.f) ? SQRT2F : (0.2f * SQRT2F);
                    size_t oidx = (((size_t)n * COUT + co) * H + gy) * W + colBase + cb + h * 8;
                    if (FUSE) v = (v + skipup[oidx]) * INV_SQRT2F;
                    outp[oidx] = v;
                }
            }
        }
    }
}

// ---------------- launch ----------------
extern "C" void kernel_launch(void* const* d_in, const int* in_sizes, int n_in,
                              void* d_out, int out_size)
{
    const float* x   = (const float*)d_in[0];
    const float* w1  = (const float*)d_in[1];
    const float* b1  = (const float*)d_in[2];
    const float* w2  = (const float*)d_in[3];
    const float* b2  = (const float*)d_in[4];
    const float* wsk = (const float*)d_in[5];
    float* out = (float*)d_out;

    void *p0, *p1, *p2, *p3, *p4, *p5, *p6, *p7;
    cudaGetSymbolAddress(&p0, g_tmp1);
    cudaGetSymbolAddress(&p1, g_up);
    cudaGetSymbolAddress(&p2, g_skip);
    cudaGetSymbolAddress(&p3, g_skipup);
    cudaGetSymbolAddress(&p4, g_w1t);
    cudaGetSymbolAddress(&p5, g_w2t);
    cudaGetSymbolAddress(&p6, g_wskt);
    cudaGetSymbolAddress(&p7, g_xr);
    float* tmp1   = (float*)p0;
    float* up     = (float*)p1;
    float* skip   = (float*)p2;
    float* skipup = (float*)p3;
    float* w1t    = (float*)p4;
    float* w2t    = (float*)p5;
    float* wskt   = (float*)p6;
    float* xr     = (float*)p7;

    const float scale3 = 1.0f / 48.0f;   // 1/sqrt(256*9)
    const float scale1 = 1.0f / 16.0f;   // 1/sqrt(256)

    auto kconv1 = conv_mma_kernel<2, 64, 64, 3, 256, true, false>;
    auto kconv2 = conv_mma_kernel<2, 128, 128, 3, 128, true, true>;
    auto kskip  = conv_mma_kernel<2, 64, 64, 1, 128, false, false>;

    constexpr int SM_CV = 2 * (9 * 8 * 136 + 8 * 4 * cpad_calc(4, 66)) * 4;  // 95232
    constexpr int SM_SK = 2 * (1 * 8 * 136 + 8 * 2 * cpad_calc(2, 64)) * 4;  // 17408

    cudaFuncSetAttribute(kconv1, cudaFuncAttributeMaxDynamicSharedMemorySize, SM_CV);
    cudaFuncSetAttribute(kconv2, cudaFuncAttributeMaxDynamicSharedMemorySize, SM_CV);
    cudaFuncSetAttribute(kskip,  cudaFuncAttributeMaxDynamicSharedMemorySize, SM_SK);

    // prep: tf32-round x, transpose+round+scale weights
    round_tf32_kernel<<<32768, 256>>>(x, xr, 8 * 256 * 64 * 64);
    transpose_w3_kernel<<<2304, 256>>>(w1, w1t, 256, scale3);
    transpose_w3_kernel<<<1152, 256>>>(w2, w2t, 128, scale3);
    transpose_w1x1_kernel<<<128, 256>>>(wsk, wskt, scale1);

    // skip: 1x1 conv at 64x64 (commuted past upsample), then upsample to 128^2 (fp32)
    kskip<<<dim3(32, 1, 8), 256, SM_SK>>>(xr, wskt, nullptr, nullptr, skip);
    upsample2x_kernel<false><<<65536, 256>>>(skip, skipup, 8 * 128 * 128 * 128);

    // conv1 + FusedLeakyReLU at 64x64 (fp32 out)
    kconv1<<<dim3(32, 2, 8), 256, SM_CV>>>(xr, w1t, b1, nullptr, tmp1);

    // bilinear 2x upsample of activations, tf32-rounded for conv2
    upsample2x_kernel<true><<<131072, 256>>>(tmp1, up, 8 * 256 * 128 * 128);

    // conv2 + FusedLeakyReLU at 128^2, fused skip add + /sqrt(2)
    kconv2<<<dim3(128, 1, 8), 256, SM_CV>>>(up, w2t, b2, skipup, out);
}

// round 5
// speedup vs baseline: 5.4983x; 1.0025x over previous
#include <cuda_runtime.h>
#include <cstdint>

#define CIN 256
#define SQRT2F 1.41421356237309515f
#define INV_SQRT2F 0.70710678118654752f

// ---------------- scratch (device globals: no cudaMalloc allowed) ----------------
__device__ float g_xr    [8u * 256u * 64u * 64u];     // tf32-rounded x
__device__ float g_tmp1  [8u * 256u * 64u * 64u];     // conv1 output (post-act, fp32)
__device__ float g_up    [8u * 256u * 128u * 128u];   // upsampled conv1 out (tf32-rounded)
__device__ float g_skip  [8u * 128u * 64u * 64u];     // 1x1 skip at 64x64 (fp32)
__device__ float g_skipup[8u * 128u * 128u * 128u];   // upsampled skip at 128x128 (fp32)
__device__ float g_w1t [256u * 9u * 256u];            // [ci][tap][co], tf32, scaled
__device__ float g_w2t [256u * 9u * 128u];
__device__ float g_wskt[256u * 128u];

// ---------------- small helpers ----------------
__device__ __forceinline__ uint32_t f2tf32(float x)
{
    uint32_t u;
    asm("cvt.rna.tf32.f32 %0, %1;" : "=r"(u) : "f"(x));
    return u;
}

__device__ __forceinline__ void mma_tf32(float* c, const uint32_t* a, const uint32_t* b)
{
    asm volatile(
        "mma.sync.aligned.m16n8k8.row.col.f32.tf32.tf32.f32 "
        "{%0,%1,%2,%3}, {%4,%5,%6,%7}, {%8,%9}, {%0,%1,%2,%3};"
        : "+f"(c[0]), "+f"(c[1]), "+f"(c[2]), "+f"(c[3])
        : "r"(a[0]), "r"(a[1]), "r"(a[2]), "r"(a[3]), "r"(b[0]), "r"(b[1]));
}

__device__ __forceinline__ void cp_async4_z(float* dst, const float* src, bool ok)
{
    uint32_t d = (uint32_t)__cvta_generic_to_shared(dst);
    int sz = ok ? 4 : 0;     // src-size 0 -> zero fill (halo)
    asm volatile("cp.async.ca.shared.global [%0], [%1], 4, %2;" :: "r"(d), "l"(src), "r"(sz));
}
__device__ __forceinline__ void cp_async16(float* dst, const float* src)
{
    uint32_t d = (uint32_t)__cvta_generic_to_shared(dst);
    asm volatile("cp.async.cg.shared.global [%0], [%1], 16;" :: "r"(d), "l"(src));
}
__device__ __forceinline__ void cp_commit() { asm volatile("cp.async.commit_group;"); }
template <int N>
__device__ __forceinline__ void cp_wait() { asm volatile("cp.async.wait_group %0;" :: "n"(N)); }

// bilinear 2x upsample taps (half-pixel centers, edge clamp)
__device__ __forceinline__ void up_taps(int o, int lim, int& a, int& b, float& fa, float& fb)
{
    int i = o >> 1;
    if (o & 1) { a = i;                    b = (i + 1 < lim) ? i + 1 : lim; fa = 0.75f; fb = 0.25f; }
    else       { a = (i - 1 > 0) ? i - 1 : 0; b = i;                        fa = 0.25f; fb = 0.75f; }
}

// smallest pad >= cw with (xr*pad) % 32 == 8  (conflict-free fragment LDS)
__host__ __device__ constexpr int cpad_calc(int xr, int cw)
{
    int p = cw;
    while ((xr * p) % 32 != 8) p++;
    return p;
}

// ---------------- prep kernels ----------------
__global__ void round_tf32_kernel(const float* __restrict__ src, float* __restrict__ dst,
                                  int total)
{
    int i = blockIdx.x * 256 + threadIdx.x;
    if (i < total) dst[i] = __uint_as_float(f2tf32(src[i]));
}

__global__ void transpose_w3_kernel(const float* __restrict__ w, float* __restrict__ wt,
                                    int cout, float scale)
{
    int idx = blockIdx.x * 256 + threadIdx.x;
    if (idx >= cout * 2304) return;
    int co  = idx / 2304;
    int rem = idx - co * 2304;
    int ci  = rem / 9;
    int tap = rem - ci * 9;
    wt[((size_t)ci * 9 + tap) * cout + co] = __uint_as_float(f2tf32(w[idx] * scale));
}

__global__ void transpose_w1x1_kernel(const float* __restrict__ w, float* __restrict__ wt,
                                      float scale)
{
    int idx = blockIdx.x * 256 + threadIdx.x;   // 32768 exact
    int co = idx >> 8;
    int ci = idx & 255;
    wt[ci * 128 + co] = __uint_as_float(f2tf32(w[idx] * scale));
}

template <bool ROUND>
__global__ void upsample2x_kernel(const float* __restrict__ src, float* __restrict__ dst,
                                  int total)
{
    int idx = blockIdx.x * 256 + threadIdx.x;
    if (idx >= total) return;
    int c   = idx >> 14;
    int rem = idx & 16383;
    int oh  = rem >> 7;
    int ow  = rem & 127;
    int ha, hb, wa, wb; float fha, fhb, fwa, fwb;
    up_taps(oh, 63, ha, hb, fha, fhb);
    up_taps(ow, 63, wa, wb, fwa, fwb);
    const float* S = src + (size_t)c * 4096;
    float v = fha * (fwa * S[ha * 64 + wa] + fwb * S[ha * 64 + wb]) +
              fhb * (fwa * S[hb * 64 + wa] + fwb * S[hb * 64 + wb]);
    dst[idx] = ROUND ? __uint_as_float(f2tf32(v)) : v;
}

// ---------------- tf32 tensor-core implicit-GEMM conv, cp.async 2-stage pipeline ----
// Block: 256 thr (8 warps). Output tile: 128 px (TH rows x 64 cols) x 128 co.
// Warp tile: 64 px x 32 co = 4 m-frags x 4 n-frags of m16n8k8.
template <int TH, int H, int W, int KS, int COUT, bool ACT, bool FUSE>
__global__ __launch_bounds__(256, 2)
void conv_mma_kernel(const float* __restrict__ in, const float* __restrict__ wt,
                     const float* __restrict__ bias, const float* __restrict__ skipup,
                     float* __restrict__ outp)
{
    constexpr int KS2   = KS * KS;
    constexpr int PAD   = (KS == 3) ? 1 : 0;
    constexpr int TWID  = 64;
    constexpr int XR    = TH + KS - 1;
    constexpr int CW    = TWID + 2 * PAD;
    constexpr int CPAD  = cpad_calc(XR, CW);
    constexpr int XRC   = XR * CPAD;          // per-ci stride, == 8 mod 32
    constexpr int WST   = 136;                // per-(tap,ci) stride, == 8 mod 32
    constexpr int WSTG  = KS2 * 8 * WST;
    constexpr int XSTG  = 8 * XRC;
    constexpr int STAGE = WSTG + XSTG;
    constexpr int NCH   = CIN / 8;

    extern __shared__ float smem[];

    const int tid   = threadIdx.x;
    const int lane  = tid & 31;
    const int warp  = tid >> 5;
    const int g     = lane >> 2;
    const int t     = lane & 3;
    const int warpM = warp & 1;     // row within px tile
    const int warpN = warp >> 1;    // co quarter (32 co)

    const int n       = blockIdx.z;
    const int coBase  = blockIdx.y * 128;
    constexpr int tilesX = W / TWID;
    const int colBase = (blockIdx.x % tilesX) * TWID;
    const int rowBase = (blockIdx.x / tilesX) * TH;

    const float* inN = in + (size_t)n * CIN * H * W;

    // ---- staging (cp.async) ----
    auto stage = [&](int chunk) {
        float* base = smem + (chunk & 1) * STAGE;
        float* Wsb  = base;
        float* Xsb  = base + WSTG;
        const int ciB = chunk * 8;
        // weights: 16B vectors, fully coalesced
#pragma unroll
        for (int idx = tid; idx < KS2 * 8 * 32; idx += 256) {
            int q   = idx & 31;
            int ci  = (idx >> 5) & 7;
            int tap = idx >> 8;
            cp_async16(&Wsb[(tap * 8 + ci) * WST + q * 4],
                       &wt[((size_t)(ciB + ci) * KS2 + tap) * COUT + coBase + q * 4]);
        }
        // input halo tile: 4B with zero-fill at borders
#pragma unroll
        for (int idx = tid; idx < 8 * XR * CW; idx += 256) {
            int ci  = idx / (XR * CW);
            int rem = idx - ci * (XR * CW);
            int rr  = rem / CW;
            int cc  = rem - rr * CW;
            int gy  = rowBase + rr - PAD;
            int gx  = colBase + cc - PAD;
            bool ok = ((unsigned)gy < (unsigned)H) && ((unsigned)gx < (unsigned)W);
            const float* src = ok ? &inN[(size_t)(ciB + ci) * H * W + gy * W + gx] : inN;
            cp_async4_z(&Xsb[ci * XRC + rr * CPAD + cc], src, ok);
        }
    };

    float acc[4][4][4];
#pragma unroll
    for (int i = 0; i < 4; i++)
#pragma unroll
        for (int j = 0; j < 4; j++)
#pragma unroll
            for (int k = 0; k < 4; k++) acc[i][j][k] = 0.f;

    stage(0); cp_commit();
    stage(1); cp_commit();

    for (int c = 0; c < NCH; c++) {
        if (c + 1 < NCH) cp_wait<1>(); else cp_wait<0>();
        __syncthreads();

        const float* base = smem + (c & 1) * STAGE;
        const float* Wsb  = base;
        const float* Xsb  = base + WSTG;

#pragma unroll
        for (int ky = 0; ky < KS; ky++)
#pragma unroll
            for (int kx = 0; kx < KS; kx++) {
                const int tap = ky * KS + kx;
                uint32_t a[4][4], b[4][2];
#pragma unroll
                for (int mf = 0; mf < 4; mf++) {
                    const int cb = mf * 16 + g;
                    const float* p = &Xsb[(warpM + ky) * CPAD + cb + kx];
                    a[mf][0] = __float_as_uint(p[t * XRC]);
                    a[mf][1] = __float_as_uint(p[t * XRC + 8]);
                    a[mf][2] = __float_as_uint(p[(t + 4) * XRC]);
                    a[mf][3] = __float_as_uint(p[(t + 4) * XRC + 8]);
                }
#pragma unroll
                for (int nf = 0; nf < 4; nf++) {
                    const int co = warpN * 32 + nf * 8 + g;
                    b[nf][0] = __float_as_uint(Wsb[(tap * 8 + t) * WST + co]);
                    b[nf][1] = __float_as_uint(Wsb[(tap * 8 + t + 4) * WST + co]);
                }
#pragma unroll
                for (int mf = 0; mf < 4; mf++)
#pragma unroll
                    for (int nf = 0; nf < 4; nf++)
                        mma_tf32(acc[mf][nf], a[mf], b[nf]);
            }
        __syncthreads();

        if (c + 2 < NCH) { stage(c + 2); cp_commit(); }
    }

    // ---- epilogue: bias + leaky*sqrt2 [+ skip add, /sqrt2] ----
    const int gy = rowBase + warpM;
#pragma unroll
    for (int nf = 0; nf < 4; nf++) {
#pragma unroll
        for (int q = 0; q < 2; q++) {
            const int co = coBase + warpN * 32 + nf * 8 + t * 2 + q;
            const float bv = ACT ? __ldg(&bias[co]) : 0.f;
#pragma unroll
            for (int mf = 0; mf < 4; mf++) {
                const int cb = mf * 16 + g;
#pragma unroll
                for (int h = 0; h < 2; h++) {
                    float v = acc[mf][nf][h * 2 + q] + bv;
                    if (ACT) v *= (v >= 0.f) ? SQRT2F : (0.2f * SQRT2F);
                    size_t oidx = (((size_t)n * COUT + co) * H + gy) * W + colBase + cb + h * 8;
                    if (FUSE) v = (v + skipup[oidx]) * INV_SQRT2F;
                    outp[oidx] = v;
                }
            }
        }
    }
}

// ---------------- launch ----------------
extern "C" void kernel_launch(void* const* d_in, const int* in_sizes, int n_in,
                              void* d_out, int out_size)
{
    const float* x   = (const float*)d_in[0];
    const float* w1  = (const float*)d_in[1];
    const float* b1  = (const float*)d_in[2];
    const float* w2  = (const float*)d_in[3];
    const float* b2  = (const float*)d_in[4];
    const float* wsk = (const float*)d_in[5];
    float* out = (float*)d_out;

    void *p0, *p1, *p2, *p3, *p4, *p5, *p6, *p7;
    cudaGetSymbolAddress(&p0, g_tmp1);
    cudaGetSymbolAddress(&p1, g_up);
    cudaGetSymbolAddress(&p2, g_skip);
    cudaGetSymbolAddress(&p3, g_skipup);
    cudaGetSymbolAddress(&p4, g_w1t);
    cudaGetSymbolAddress(&p5, g_w2t);
    cudaGetSymbolAddress(&p6, g_wskt);
    cudaGetSymbolAddress(&p7, g_xr);
    float* tmp1   = (float*)p0;
    float* up     = (float*)p1;
    float* skip   = (float*)p2;
    float* skipup = (float*)p3;
    float* w1t    = (float*)p4;
    float* w2t    = (float*)p5;
    float* wskt   = (float*)p6;
    float* xr     = (float*)p7;

    const float scale3 = 1.0f / 48.0f;   // 1/sqrt(256*9)
    const float scale1 = 1.0f / 16.0f;   // 1/sqrt(256)

    auto kconv1 = conv_mma_kernel<2, 64, 64, 3, 256, true, false>;
    auto kconv2 = conv_mma_kernel<2, 128, 128, 3, 128, true, true>;
    auto kskip  = conv_mma_kernel<2, 64, 64, 1, 128, false, false>;

    constexpr int SM_CV = 2 * (9 * 8 * 136 + 8 * 4 * cpad_calc(4, 66)) * 4;  // 95232
    constexpr int SM_SK = 2 * (1 * 8 * 136 + 8 * 2 * cpad_calc(2, 64)) * 4;  // 17408

    cudaFuncSetAttribute(kconv1, cudaFuncAttributeMaxDynamicSharedMemorySize, SM_CV);
    cudaFuncSetAttribute(kconv2, cudaFuncAttributeMaxDynamicSharedMemorySize, SM_CV);
    cudaFuncSetAttribute(kskip,  cudaFuncAttributeMaxDynamicSharedMemorySize, SM_SK);

    // prep: tf32-round x, transpose+round+scale weights
    round_tf32_kernel<<<32768, 256>>>(x, xr, 8 * 256 * 64 * 64);
    transpose_w3_kernel<<<2304, 256>>>(w1, w1t, 256, scale3);
    transpose_w3_kernel<<<1152, 256>>>(w2, w2t, 128, scale3);
    transpose_w1x1_kernel<<<128, 256>>>(wsk, wskt, scale1);

    // skip: 1x1 conv at 64x64 (commuted past upsample), then upsample to 128^2 (fp32)
    kskip<<<dim3(32, 1, 8), 256, SM_SK>>>(xr, wskt, nullptr, nullptr, skip);
    upsample2x_kernel<false><<<65536, 256>>>(skip, skipup, 8 * 128 * 128 * 128);

    // conv1 + FusedLeakyReLU at 64x64 (fp32 out)
    kconv1<<<dim3(32, 2, 8), 256, SM_CV>>>(xr, w1t, b1, nullptr, tmp1);

    // bilinear 2x upsample of activations, tf32-rounded for conv2
    upsample2x_kernel<true><<<131072, 256>>>(tmp1, up, 8 * 256 * 128 * 128);

    // conv2 + FusedLeakyReLU at 128^2, fused skip add + /sqrt(2)
    kconv2<<<dim3(128, 1, 8), 256, SM_CV>>>(up, w2t, b2, skipup, out);
}

// round 6
// speedup vs baseline: 5.5052x; 1.0013x over previous
#include <cuda_runtime.h>
#include <cstdint>

#define CIN 256
#define SQRT2F 1.41421356237309515f
#define INV_SQRT2F 0.70710678118654752f

// ---------------- scratch (device globals: no cudaMalloc allowed) ----------------
__device__ float g_xr    [8u * 256u * 64u * 64u];     // tf32-rounded x
__device__ float g_tmp1  [8u * 256u * 64u * 64u];     // conv1 output (post-act, fp32)
__device__ float g_up    [8u * 256u * 128u * 128u];   // upsampled conv1 out (tf32-rounded)
__device__ float g_skip  [8u * 128u * 64u * 64u];     // 1x1 skip at 64x64 (fp32)
__device__ float g_skipup[8u * 128u * 128u * 128u];   // upsampled skip at 128x128 (fp32)
__device__ float g_w1t [256u * 9u * 256u];            // [ci][tap][co], tf32, scaled
__device__ float g_w2t [256u * 9u * 128u];
__device__ float g_wskt[256u * 128u];

// ---------------- small helpers ----------------
__device__ __forceinline__ uint32_t f2tf32(float x)
{
    uint32_t u;
    asm("cvt.rna.tf32.f32 %0, %1;" : "=r"(u) : "f"(x));
    return u;
}

__device__ __forceinline__ void mma_tf32(float* c, const uint32_t* a, const uint32_t* b)
{
    asm volatile(
        "mma.sync.aligned.m16n8k8.row.col.f32.tf32.tf32.f32 "
        "{%0,%1,%2,%3}, {%4,%5,%6,%7}, {%8,%9}, {%0,%1,%2,%3};"
        : "+f"(c[0]), "+f"(c[1]), "+f"(c[2]), "+f"(c[3])
        : "r"(a[0]), "r"(a[1]), "r"(a[2]), "r"(a[3]), "r"(b[0]), "r"(b[1]));
}

__device__ __forceinline__ void cp_async4_z(float* dst, const float* src, bool ok)
{
    uint32_t d = (uint32_t)__cvta_generic_to_shared(dst);
    int sz = ok ? 4 : 0;     // src-size 0 -> zero fill (halo)
    asm volatile("cp.async.ca.shared.global [%0], [%1], 4, %2;" :: "r"(d), "l"(src), "r"(sz));
}
__device__ __forceinline__ void cp_async16(float* dst, const float* src)
{
    uint32_t d = (uint32_t)__cvta_generic_to_shared(dst);
    asm volatile("cp.async.cg.shared.global [%0], [%1], 16;" :: "r"(d), "l"(src));
}
__device__ __forceinline__ void cp_commit() { asm volatile("cp.async.commit_group;"); }
template <int N>
__device__ __forceinline__ void cp_wait() { asm volatile("cp.async.wait_group %0;" :: "n"(N)); }

// bilinear 2x upsample taps (half-pixel centers, edge clamp)
__device__ __forceinline__ void up_taps(int o, int lim, int& a, int& b, float& fa, float& fb)
{
    int i = o >> 1;
    if (o & 1) { a = i;                    b = (i + 1 < lim) ? i + 1 : lim; fa = 0.75f; fb = 0.25f; }
    else       { a = (i - 1 > 0) ? i - 1 : 0; b = i;                        fa = 0.25f; fb = 0.75f; }
}

// smallest pad >= cw with (xr*pad) % 32 == 8  (conflict-free fragment LDS)
__host__ __device__ constexpr int cpad_calc(int xr, int cw)
{
    int p = cw;
    while ((xr * p) % 32 != 8) p++;
    return p;
}

// ---------------- prep kernels ----------------
__global__ void round_tf32_kernel(const float* __restrict__ src, float* __restrict__ dst,
                                  int total)
{
    int i = blockIdx.x * 256 + threadIdx.x;
    if (i < total) dst[i] = __uint_as_float(f2tf32(src[i]));
}

__global__ void transpose_w3_kernel(const float* __restrict__ w, float* __restrict__ wt,
                                    int cout, float scale)
{
    int idx = blockIdx.x * 256 + threadIdx.x;
    if (idx >= cout * 2304) return;
    int co  = idx / 2304;
    int rem = idx - co * 2304;
    int ci  = rem / 9;
    int tap = rem - ci * 9;
    wt[((size_t)ci * 9 + tap) * cout + co] = __uint_as_float(f2tf32(w[idx] * scale));
}

__global__ void transpose_w1x1_kernel(const float* __restrict__ w, float* __restrict__ wt,
                                      float scale)
{
    int idx = blockIdx.x * 256 + threadIdx.x;   // 32768 exact
    int co = idx >> 8;
    int ci = idx & 255;
    wt[ci * 128 + co] = __uint_as_float(f2tf32(w[idx] * scale));
}

template <bool ROUND>
__global__ void upsample2x_kernel(const float* __restrict__ src, float* __restrict__ dst,
                                  int total)
{
    int idx = blockIdx.x * 256 + threadIdx.x;
    if (idx >= total) return;
    int c   = idx >> 14;
    int rem = idx & 16383;
    int oh  = rem >> 7;
    int ow  = rem & 127;
    int ha, hb, wa, wb; float fha, fhb, fwa, fwb;
    up_taps(oh, 63, ha, hb, fha, fhb);
    up_taps(ow, 63, wa, wb, fwa, fwb);
    const float* S = src + (size_t)c * 4096;
    float v = fha * (fwa * S[ha * 64 + wa] + fwb * S[ha * 64 + wb]) +
              fhb * (fwa * S[hb * 64 + wa] + fwb * S[hb * 64 + wb]);
    dst[idx] = ROUND ? __uint_as_float(f2tf32(v)) : v;
}

// ---------------- tf32 tensor-core implicit-GEMM conv, cp.async 2-stage pipeline ----
// Block: 256 thr (8 warps). Output tile: 128 px (TH rows x 64 cols) x 128 co.
// Warp tile: 64 px x 32 co = 4 m-frags x 4 n-frags of m16n8k8.
template <int TH, int H, int W, int KS, int COUT, bool ACT, bool FUSE>
__global__ __launch_bounds__(256, 2)
void conv_mma_kernel(const float* __restrict__ in, const float* __restrict__ wt,
                     const float* __restrict__ bias, const float* __restrict__ skipup,
                     float* __restrict__ outp)
{
    constexpr int KS2   = KS * KS;
    constexpr int PAD   = (KS == 3) ? 1 : 0;
    constexpr int TWID  = 64;
    constexpr int XR    = TH + KS - 1;
    constexpr int CW    = TWID + 2 * PAD;
    constexpr int CPAD  = cpad_calc(XR, CW);
    constexpr int XRC   = XR * CPAD;          // per-ci stride, == 8 mod 32
    constexpr int WST   = 136;                // per-(tap,ci) stride, == 8 mod 32
    constexpr int WSTG  = KS2 * 8 * WST;
    constexpr int XSTG  = 8 * XRC;
    constexpr int STAGE = WSTG + XSTG;
    constexpr int NCH   = CIN / 8;

    extern __shared__ float smem[];

    const int tid   = threadIdx.x;
    const int lane  = tid & 31;
    const int warp  = tid >> 5;
    const int g     = lane >> 2;
    const int t     = lane & 3;
    const int warpM = warp & 1;     // row within px tile
    const int warpN = warp >> 1;    // co quarter (32 co)

    const int n       = blockIdx.z;
    const int coBase  = blockIdx.y * 128;
    constexpr int tilesX = W / TWID;
    const int colBase = (blockIdx.x % tilesX) * TWID;
    const int rowBase = (blockIdx.x / tilesX) * TH;

    const float* inN = in + (size_t)n * CIN * H * W;

    // ---- staging (cp.async) ----
    auto stage = [&](int chunk) {
        float* base = smem + (chunk & 1) * STAGE;
        float* Wsb  = base;
        float* Xsb  = base + WSTG;
        const int ciB = chunk * 8;
        // weights: 16B vectors, fully coalesced
#pragma unroll
        for (int idx = tid; idx < KS2 * 8 * 32; idx += 256) {
            int q   = idx & 31;
            int ci  = (idx >> 5) & 7;
            int tap = idx >> 8;
            cp_async16(&Wsb[(tap * 8 + ci) * WST + q * 4],
                       &wt[((size_t)(ciB + ci) * KS2 + tap) * COUT + coBase + q * 4]);
        }
        // input halo tile: 4B with zero-fill at borders
#pragma unroll
        for (int idx = tid; idx < 8 * XR * CW; idx += 256) {
            int ci  = idx / (XR * CW);
            int rem = idx - ci * (XR * CW);
            int rr  = rem / CW;
            int cc  = rem - rr * CW;
            int gy  = rowBase + rr - PAD;
            int gx  = colBase + cc - PAD;
            bool ok = ((unsigned)gy < (unsigned)H) && ((unsigned)gx < (unsigned)W);
            const float* src = ok ? &inN[(size_t)(ciB + ci) * H * W + gy * W + gx] : inN;
            cp_async4_z(&Xsb[ci * XRC + rr * CPAD + cc], src, ok);
        }
    };

    float acc[4][4][4];
#pragma unroll
    for (int i = 0; i < 4; i++)
#pragma unroll
        for (int j = 0; j < 4; j++)
#pragma unroll
            for (int k = 0; k < 4; k++) acc[i][j][k] = 0.f;

    stage(0); cp_commit();
    stage(1); cp_commit();

    for (int c = 0; c < NCH; c++) {
        if (c + 1 < NCH) cp_wait<1>(); else cp_wait<0>();
        __syncthreads();

        const float* base = smem + (c & 1) * STAGE;
        const float* Wsb  = base;
        const float* Xsb  = base + WSTG;

#pragma unroll
        for (int ky = 0; ky < KS; ky++)
#pragma unroll
            for (int kx = 0; kx < KS; kx++) {
                const int tap = ky * KS + kx;
                uint32_t a[4][4], b[4][2];
#pragma unroll
                for (int mf = 0; mf < 4; mf++) {
                    const int cb = mf * 16 + g;
                    const float* p = &Xsb[(warpM + ky) * CPAD + cb + kx];
                    a[mf][0] = __float_as_uint(p[t * XRC]);
                    a[mf][1] = __float_as_uint(p[t * XRC + 8]);
                    a[mf][2] = __float_as_uint(p[(t + 4) * XRC]);
                    a[mf][3] = __float_as_uint(p[(t + 4) * XRC + 8]);
                }
#pragma unroll
                for (int nf = 0; nf < 4; nf++) {
                    const int co = warpN * 32 + nf * 8 + g;
                    b[nf][0] = __float_as_uint(Wsb[(tap * 8 + t) * WST + co]);
                    b[nf][1] = __float_as_uint(Wsb[(tap * 8 + t + 4) * WST + co]);
                }
#pragma unroll
                for (int mf = 0; mf < 4; mf++)
#pragma unroll
                    for (int nf = 0; nf < 4; nf++)
                        mma_tf32(acc[mf][nf], a[mf], b[nf]);
            }
        __syncthreads();

        if (c + 2 < NCH) { stage(c + 2); cp_commit(); }
    }

    // ---- epilogue: bias + leaky*sqrt2 [+ skip add, /sqrt2] ----
    const int gy = rowBase + warpM;
#pragma unroll
    for (int nf = 0; nf < 4; nf++) {
#pragma unroll
        for (int q = 0; q < 2; q++) {
            const int co = coBase + warpN * 32 + nf * 8 + t * 2 + q;
            const float bv = ACT ? __ldg(&bias[co]) : 0.f;
#pragma unroll
            for (int mf = 0; mf < 4; mf++) {
                const int cb = mf * 16 + g;
#pragma unroll
                for (int h = 0; h < 2; h++) {
                    float v = acc[mf][nf][h * 2 + q] + bv;
                    if (ACT) v *= (v >= 0.f) ? SQRT2F : (0.2f * SQRT2F);
                    size_t oidx = (((size_t)n * COUT + co) * H + gy) * W + colBase + cb + h * 8;
                    if (FUSE) v = (v + skipup[oidx]) * INV_SQRT2F;
                    outp[oidx] = v;
                }
            }
        }
    }
}

// ---------------- launch ----------------
extern "C" void kernel_launch(void* const* d_in, const int* in_sizes, int n_in,
                              void* d_out, int out_size)
{
    const float* x   = (const float*)d_in[0];
    const float* w1  = (const float*)d_in[1];
    const float* b1  = (const float*)d_in[2];
    const float* w2  = (const float*)d_in[3];
    const float* b2  = (const float*)d_in[4];
    const float* wsk = (const float*)d_in[5];
    float* out = (float*)d_out;

    void *p0, *p1, *p2, *p3, *p4, *p5, *p6, *p7;
    cudaGetSymbolAddress(&p0, g_tmp1);
    cudaGetSymbolAddress(&p1, g_up);
    cudaGetSymbolAddress(&p2, g_skip);
    cudaGetSymbolAddress(&p3, g_skipup);
    cudaGetSymbolAddress(&p4, g_w1t);
    cudaGetSymbolAddress(&p5, g_w2t);
    cudaGetSymbolAddress(&p6, g_wskt);
    cudaGetSymbolAddress(&p7, g_xr);
    float* tmp1   = (float*)p0;
    float* up     = (float*)p1;
    float* skip   = (float*)p2;
    float* skipup = (float*)p3;
    float* w1t    = (float*)p4;
    float* w2t    = (float*)p5;
    float* wskt   = (float*)p6;
    float* xr     = (float*)p7;

    const float scale3 = 1.0f / 48.0f;   // 1/sqrt(256*9)
    const float scale1 = 1.0f / 16.0f;   // 1/sqrt(256)

    auto kconv1 = conv_mma_kernel<2, 64, 64, 3, 256, true, false>;
    auto kconv2 = conv_mma_kernel<2, 128, 128, 3, 128, true, true>;
    auto kskip  = conv_mma_kernel<2, 64, 64, 1, 128, false, false>;

    constexpr int SM_CV = 2 * (9 * 8 * 136 + 8 * 4 * cpad_calc(4, 66)) * 4;  // 95232
    constexpr int SM_SK = 2 * (1 * 8 * 136 + 8 * 2 * cpad_calc(2, 64)) * 4;  // 17408

    cudaFuncSetAttribute(kconv1, cudaFuncAttributeMaxDynamicSharedMemorySize, SM_CV);
    cudaFuncSetAttribute(kconv2, cudaFuncAttributeMaxDynamicSharedMemorySize, SM_CV);
    cudaFuncSetAttribute(kskip,  cudaFuncAttributeMaxDynamicSharedMemorySize, SM_SK);

    // prep: tf32-round x, transpose+round+scale weights
    round_tf32_kernel<<<32768, 256>>>(x, xr, 8 * 256 * 64 * 64);
    transpose_w3_kernel<<<2304, 256>>>(w1, w1t, 256, scale3);
    transpose_w3_kernel<<<1152, 256>>>(w2, w2t, 128, scale3);
    transpose_w1x1_kernel<<<128, 256>>>(wsk, wskt, scale1);

    // skip: 1x1 conv at 64x64 (commuted past upsample), then upsample to 128^2 (fp32)
    kskip<<<dim3(32, 1, 8), 256, SM_SK>>>(xr, wskt, nullptr, nullptr, skip);
    upsample2x_kernel<false><<<65536, 256>>>(skip, skipup, 8 * 128 * 128 * 128);

    // conv1 + FusedLeakyReLU at 64x64 (fp32 out)
    kconv1<<<dim3(32, 2, 8), 256, SM_CV>>>(xr, w1t, b1, nullptr, tmp1);

    // bilinear 2x upsample of activations, tf32-rounded for conv2
    upsample2x_kernel<true><<<131072, 256>>>(tmp1, up, 8 * 256 * 128 * 128);

    // conv2 + FusedLeakyReLU at 128^2, fused skip add + /sqrt(2)
    kconv2<<<dim3(128, 1, 8), 256, SM_CV>>>(up, w2t, b2, skipup, out);
}

// round 7
// speedup vs baseline: 5.5399x; 1.0063x over previous
#include <cuda_runtime.h>
#include <cstdint>

#define CIN 256
#define SQRT2F 1.41421356237309515f
#define INV_SQRT2F 0.70710678118654752f

// ---------------- scratch (device globals: no cudaMalloc allowed) ----------------
__device__ float g_xr    [8u * 256u * 64u * 64u];     // tf32-rounded x
__device__ float g_tmp1  [8u * 256u * 64u * 64u];     // conv1 output (post-act, fp32)
__device__ float g_up    [8u * 256u * 128u * 128u];   // upsampled conv1 out (tf32-rounded)
__device__ float g_skip  [8u * 128u * 64u * 64u];     // 1x1 skip at 64x64 (fp32)
__device__ float g_w1t [256u * 9u * 256u];            // [ci][tap][co], tf32, scaled
__device__ float g_w2t [256u * 9u * 128u];
__device__ float g_wskt[256u * 128u];

// ---------------- small helpers ----------------
__device__ __forceinline__ uint32_t f2tf32(float x)
{
    uint32_t u;
    asm("cvt.rna.tf32.f32 %0, %1;" : "=r"(u) : "f"(x));
    return u;
}

__device__ __forceinline__ void mma_tf32(float* c, const uint32_t* a, const uint32_t* b)
{
    asm volatile(
        "mma.sync.aligned.m16n8k8.row.col.f32.tf32.tf32.f32 "
        "{%0,%1,%2,%3}, {%4,%5,%6,%7}, {%8,%9}, {%0,%1,%2,%3};"
        : "+f"(c[0]), "+f"(c[1]), "+f"(c[2]), "+f"(c[3])
        : "r"(a[0]), "r"(a[1]), "r"(a[2]), "r"(a[3]), "r"(b[0]), "r"(b[1]));
}

__device__ __forceinline__ void cp_async4_z(float* dst, const float* src, bool ok)
{
    uint32_t d = (uint32_t)__cvta_generic_to_shared(dst);
    int sz = ok ? 4 : 0;     // src-size 0 -> zero fill (halo)
    asm volatile("cp.async.ca.shared.global [%0], [%1], 4, %2;" :: "r"(d), "l"(src), "r"(sz));
}
__device__ __forceinline__ void cp_async16(float* dst, const float* src)
{
    uint32_t d = (uint32_t)__cvta_generic_to_shared(dst);
    asm volatile("cp.async.cg.shared.global [%0], [%1], 16;" :: "r"(d), "l"(src));
}
__device__ __forceinline__ void cp_commit() { asm volatile("cp.async.commit_group;"); }
template <int N>
__device__ __forceinline__ void cp_wait() { asm volatile("cp.async.wait_group %0;" :: "n"(N)); }

// bilinear 2x upsample taps (half-pixel centers, edge clamp)
__device__ __forceinline__ void up_taps(int o, int lim, int& a, int& b, float& fa, float& fb)
{
    int i = o >> 1;
    if (o & 1) { a = i;                    b = (i + 1 < lim) ? i + 1 : lim; fa = 0.75f; fb = 0.25f; }
    else       { a = (i - 1 > 0) ? i - 1 : 0; b = i;                        fa = 0.25f; fb = 0.75f; }
}

// smallest pad >= cw with (xr*pad) % 32 == 8  (conflict-free fragment LDS)
__host__ __device__ constexpr int cpad_calc(int xr, int cw)
{
    int p = cw;
    while ((xr * p) % 32 != 8) p++;
    return p;
}

// ---------------- prep kernels ----------------
__global__ void round_tf32_kernel(const float* __restrict__ src, float* __restrict__ dst,
                                  int total)
{
    int i = blockIdx.x * 256 + threadIdx.x;
    if (i < total) dst[i] = __uint_as_float(f2tf32(src[i]));
}

__global__ void transpose_w3_kernel(const float* __restrict__ w, float* __restrict__ wt,
                                    int cout, float scale)
{
    int idx = blockIdx.x * 256 + threadIdx.x;
    if (idx >= cout * 2304) return;
    int co  = idx / 2304;
    int rem = idx - co * 2304;
    int ci  = rem / 9;
    int tap = rem - ci * 9;
    wt[((size_t)ci * 9 + tap) * cout + co] = __uint_as_float(f2tf32(w[idx] * scale));
}

__global__ void transpose_w1x1_kernel(const float* __restrict__ w, float* __restrict__ wt,
                                      float scale)
{
    int idx = blockIdx.x * 256 + threadIdx.x;   // 32768 exact
    int co = idx >> 8;
    int ci = idx & 255;
    wt[ci * 128 + co] = __uint_as_float(f2tf32(w[idx] * scale));
}

// tf32-rounding bilinear upsample (conv2 input)
__global__ void upsample2x_kernel(const float* __restrict__ src, float* __restrict__ dst,
                                  int total)
{
    int idx = blockIdx.x * 256 + threadIdx.x;
    if (idx >= total) return;
    int c   = idx >> 14;
    int rem = idx & 16383;
    int oh  = rem >> 7;
    int ow  = rem & 127;
    int ha, hb, wa, wb; float fha, fhb, fwa, fwb;
    up_taps(oh, 63, ha, hb, fha, fhb);
    up_taps(ow, 63, wa, wb, fwa, fwb);
    const float* S = src + (size_t)c * 4096;
    float v = fha * (fwa * S[ha * 64 + wa] + fwb * S[ha * 64 + wb]) +
              fhb * (fwa * S[hb * 64 + wa] + fwb * S[hb * 64 + wb]);
    dst[idx] = __uint_as_float(f2tf32(v));
}

// ---------------- tf32 mma implicit-GEMM conv, cp.async 2-stage pipeline ----------------
// Block: 256 thr (8 warps). Output tile: 256 px (4 rows x 64 cols) x 64 co.
// Warp: row (warp&3), co half (warp>>2); warp tile 64 px x 32 co = 4x4 m16n8k8 frags.
template <int H, int W, int KS, int COUT, bool ACT, bool FUSE>
__global__ __launch_bounds__(256, 2)
void conv_mma_kernel(const float* __restrict__ in, const float* __restrict__ wt,
                     const float* __restrict__ bias, const float* __restrict__ skip64,
                     float* __restrict__ outp)
{
    constexpr int KS2   = KS * KS;
    constexpr int PAD   = (KS == 3) ? 1 : 0;
    constexpr int TH    = 4;
    constexpr int XR    = TH + KS - 1;
    constexpr int CW    = 64 + 2 * PAD;
    constexpr int CPAD  = cpad_calc(XR, CW);
    constexpr int XRC   = XR * CPAD;          // per-ci stride, == 8 mod 32
    constexpr int WST   = 72;                 // per-(tap,ci) stride, == 8 mod 32
    constexpr int WSTG  = KS2 * 8 * WST;
    constexpr int XSTG  = 8 * XRC;
    constexpr int STAGE = WSTG + XSTG;
    constexpr int NCH   = CIN / 8;

    extern __shared__ float smem[];

    const int tid   = threadIdx.x;
    const int lane  = tid & 31;
    const int warp  = tid >> 5;
    const int g     = lane >> 2;
    const int t     = lane & 3;
    const int warpM = warp & 3;     // row within 4-row px tile
    const int warpN = warp >> 2;    // co half (32 co)

    const int n       = blockIdx.z;
    const int coBase  = blockIdx.y * 64;
    constexpr int tilesX = W / 64;
    const int colBase = (blockIdx.x % tilesX) * 64;
    const int rowBase = (blockIdx.x / tilesX) * TH;

    const float* inN = in + (size_t)n * CIN * H * W;

    auto stage = [&](int chunk) {
        float* base = smem + (chunk & 1) * STAGE;
        float* Wsb  = base;
        float* Xsb  = base + WSTG;
        const int ciB = chunk * 8;
#pragma unroll
        for (int idx = tid; idx < KS2 * 8 * 16; idx += 256) {
            int q   = idx & 15;
            int ci  = (idx >> 4) & 7;
            int tap = idx >> 7;
            cp_async16(&Wsb[(tap * 8 + ci) * WST + q * 4],
                       &wt[((size_t)(ciB + ci) * KS2 + tap) * COUT + coBase + q * 4]);
        }
#pragma unroll
        for (int idx = tid; idx < 8 * XR * CW; idx += 256) {
            int ci  = idx / (XR * CW);
            int rem = idx - ci * (XR * CW);
            int rr  = rem / CW;
            int cc  = rem - rr * CW;
            int gy  = rowBase + rr - PAD;
            int gx  = colBase + cc - PAD;
            bool ok = ((unsigned)gy < (unsigned)H) && ((unsigned)gx < (unsigned)W);
            const float* src = ok ? &inN[(size_t)(ciB + ci) * H * W + gy * W + gx] : inN;
            cp_async4_z(&Xsb[ci * XRC + rr * CPAD + cc], src, ok);
        }
    };

    float acc[4][4][4];
#pragma unroll
    for (int i = 0; i < 4; i++)
#pragma unroll
        for (int j = 0; j < 4; j++)
#pragma unroll
            for (int k = 0; k < 4; k++) acc[i][j][k] = 0.f;

    stage(0); cp_commit();
    stage(1); cp_commit();

    for (int c = 0; c < NCH; c++) {
        if (c + 1 < NCH) cp_wait<1>(); else cp_wait<0>();
        __syncthreads();

        const float* base = smem + (c & 1) * STAGE;
        const float* Wsb  = base;
        const float* Xsb  = base + WSTG;

#pragma unroll
        for (int ky = 0; ky < KS; ky++)
#pragma unroll
            for (int kx = 0; kx < KS; kx++) {
                const int tap = ky * KS + kx;
                uint32_t a[4][4], b[4][2];
#pragma unroll
                for (int mf = 0; mf < 4; mf++) {
                    const int cb = mf * 16 + g;
                    const float* p = &Xsb[(warpM + ky) * CPAD + cb + kx];
                    a[mf][0] = __float_as_uint(p[t * XRC]);
                    a[mf][1] = __float_as_uint(p[t * XRC + 8]);
                    a[mf][2] = __float_as_uint(p[(t + 4) * XRC]);
                    a[mf][3] = __float_as_uint(p[(t + 4) * XRC + 8]);
                }
#pragma unroll
                for (int nf = 0; nf < 4; nf++) {
                    const int co = warpN * 32 + nf * 8 + g;
                    b[nf][0] = __float_as_uint(Wsb[(tap * 8 + t) * WST + co]);
                    b[nf][1] = __float_as_uint(Wsb[(tap * 8 + t + 4) * WST + co]);
                }
#pragma unroll
                for (int mf = 0; mf < 4; mf++)
#pragma unroll
                    for (int nf = 0; nf < 4; nf++)
                        mma_tf32(acc[mf][nf], a[mf], b[nf]);
            }
        __syncthreads();

        if (c + 2 < NCH) { stage(c + 2); cp_commit(); }
    }

    // ---- epilogue: bias + leaky*sqrt2 [+ inline bilinear skip add, /sqrt2] ----
    const int gy = rowBase + warpM;
    int ha = 0, hb = 0; float fha = 0.f, fhb = 0.f;
    if (FUSE) up_taps(gy, 63, ha, hb, fha, fhb);

#pragma unroll
    for (int nf = 0; nf < 4; nf++) {
#pragma unroll
        for (int q = 0; q < 2; q++) {
            const int co = coBase + warpN * 32 + nf * 8 + t * 2 + q;
            const float bv = ACT ? __ldg(&bias[co]) : 0.f;
            const float* S = FUSE ? (skip64 + ((size_t)n * 128 + co) * 4096) : nullptr;
#pragma unroll
            for (int mf = 0; mf < 4; mf++) {
                const int cb = mf * 16 + g;
#pragma unroll
                for (int h = 0; h < 2; h++) {
                    const int gx = colBase + cb + h * 8;
                    float v = acc[mf][nf][h * 2 + q] + bv;
                    if (ACT) v *= (v >= 0.f) ? SQRT2F : (0.2f * SQRT2F);
                    size_t oidx = (((size_t)n * COUT + co) * H + gy) * W + gx;
                    if (FUSE) {
                        int wa, wb; float fwa, fwb;
                        up_taps(gx, 63, wa, wb, fwa, fwb);
                        float sk = fha * (fwa * S[ha * 64 + wa] + fwb * S[ha * 64 + wb]) +
                                   fhb * (fwa * S[hb * 64 + wa] + fwb * S[hb * 64 + wb]);
                        v = (v + sk) * INV_SQRT2F;
                    }
                    outp[oidx] = v;
                }
            }
        }
    }
}

// ---------------- launch ----------------
extern "C" void kernel_launch(void* const* d_in, const int* in_sizes, int n_in,
                              void* d_out, int out_size)
{
    const float* x   = (const float*)d_in[0];
    const float* w1  = (const float*)d_in[1];
    const float* b1  = (const float*)d_in[2];
    const float* w2  = (const float*)d_in[3];
    const float* b2  = (const float*)d_in[4];
    const float* wsk = (const float*)d_in[5];
    float* out = (float*)d_out;

    void *p0, *p1, *p2, *p4, *p5, *p6, *p7;
    cudaGetSymbolAddress(&p0, g_tmp1);
    cudaGetSymbolAddress(&p1, g_up);
    cudaGetSymbolAddress(&p2, g_skip);
    cudaGetSymbolAddress(&p4, g_w1t);
    cudaGetSymbolAddress(&p5, g_w2t);
    cudaGetSymbolAddress(&p6, g_wskt);
    cudaGetSymbolAddress(&p7, g_xr);
    float* tmp1 = (float*)p0;
    float* up   = (float*)p1;
    float* skip = (float*)p2;
    float* w1t  = (float*)p4;
    float* w2t  = (float*)p5;
    float* wskt = (float*)p6;
    float* xr   = (float*)p7;

    const float scale3 = 1.0f / 48.0f;   // 1/sqrt(256*9)
    const float scale1 = 1.0f / 16.0f;   // 1/sqrt(256)

    auto kconv1 = conv_mma_kernel<64, 64, 3, 256, true, false>;
    auto kconv2 = conv_mma_kernel<128, 128, 3, 128, true, true>;
    auto kskip  = conv_mma_kernel<64, 64, 1, 128, false, false>;

    constexpr int SM_CV = 2 * (9 * 8 * 72 + 8 * 6 * cpad_calc(6, 66)) * 4;  // 70656
    constexpr int SM_SK = 2 * (1 * 8 * 72 + 8 * 4 * cpad_calc(4, 64)) * 4;  // 21504

    cudaFuncSetAttribute(kconv1, cudaFuncAttributeMaxDynamicSharedMemorySize, SM_CV);
    cudaFuncSetAttribute(kconv2, cudaFuncAttributeMaxDynamicSharedMemorySize, SM_CV);
    cudaFuncSetAttribute(kskip,  cudaFuncAttributeMaxDynamicSharedMemorySize, SM_SK);

    // prep: tf32-round x, transpose+round+scale weights
    round_tf32_kernel<<<32768, 256>>>(x, xr, 8 * 256 * 64 * 64);
    transpose_w3_kernel<<<2304, 256>>>(w1, w1t, 256, scale3);
    transpose_w3_kernel<<<1152, 256>>>(w2, w2t, 128, scale3);
    transpose_w1x1_kernel<<<128, 256>>>(wsk, wskt, scale1);

    // skip: 1x1 conv at 64x64 (commuted past upsample); upsampled inline in conv2 epilogue
    kskip<<<dim3(16, 2, 8), 256, SM_SK>>>(xr, wskt, nullptr, nullptr, skip);

    // conv1 + FusedLeakyReLU at 64x64 (fp32 out)
    kconv1<<<dim3(16, 4, 8), 256, SM_CV>>>(xr, w1t, b1, nullptr, tmp1);

    // bilinear 2x upsample of activations, tf32-rounded for conv2
    upsample2x_kernel<<<131072, 256>>>(tmp1, up, 8 * 256 * 128 * 128);

    // conv2 + FusedLeakyReLU at 128^2, fused bilinear-skip add + /sqrt(2)
    kconv2<<<dim3(64, 2, 8), 256, SM_CV>>>(up, w2t, b2, skip, out);
}

// round 8
// speedup vs baseline: 10.0488x; 1.8139x over previous
#include <cuda_runtime.h>
#include <cuda_fp16.h>
#include <cstdint>

#define CIN2 128   // channel pairs
#define SQRT2F 1.41421356237309515f
#define INV_SQRT2F 0.70710678118654752f

// ---------------- scratch (device globals: no cudaMalloc allowed) ----------------
__device__ uint32_t g_xh  [8u * 128u * 64u * 64u];    // x, half2 ci-pair interleaved
__device__ float    g_tmp1[8u * 256u * 64u * 64u];    // conv1 out (post-act, fp32 NCHW)
__device__ uint32_t g_uph [8u * 128u * 128u * 128u];  // upsampled conv1 out, half2 pairs
__device__ float    g_skip[8u * 128u * 64u * 64u];    // 1x1 skip at 64x64 (fp32)
__device__ uint32_t g_w1t [128u * 9u * 256u];         // [ci2][tap][co] half2, scaled
__device__ uint32_t g_w2t [128u * 9u * 128u];
__device__ uint32_t g_wskt[128u * 128u];              // [ci2][co] half2

// ---------------- small helpers ----------------
__device__ __forceinline__ uint32_t pack_h2(float lo, float hi)
{
    __half2 h = __floats2half2_rn(lo, hi);
    return *reinterpret_cast<uint32_t*>(&h);
}

__device__ __forceinline__ void mma_f16(float* c, const uint32_t* a, const uint32_t* b)
{
    asm volatile(
        "mma.sync.aligned.m16n8k16.row.col.f32.f16.f16.f32 "
        "{%0,%1,%2,%3}, {%4,%5,%6,%7}, {%8,%9}, {%0,%1,%2,%3};"
        : "+f"(c[0]), "+f"(c[1]), "+f"(c[2]), "+f"(c[3])
        : "r"(a[0]), "r"(a[1]), "r"(a[2]), "r"(a[3]), "r"(b[0]), "r"(b[1]));
}

__device__ __forceinline__ void cp_async4_z(void* dst, const void* src, bool ok)
{
    uint32_t d = (uint32_t)__cvta_generic_to_shared(dst);
    int sz = ok ? 4 : 0;
    asm volatile("cp.async.ca.shared.global [%0], [%1], 4, %2;" :: "r"(d), "l"(src), "r"(sz));
}
__device__ __forceinline__ void cp_async16(void* dst, const void* src)
{
    uint32_t d = (uint32_t)__cvta_generic_to_shared(dst);
    asm volatile("cp.async.cg.shared.global [%0], [%1], 16;" :: "r"(d), "l"(src));
}
__device__ __forceinline__ void cp_commit() { asm volatile("cp.async.commit_group;"); }
template <int N>
__device__ __forceinline__ void cp_wait() { asm volatile("cp.async.wait_group %0;" :: "n"(N)); }

__device__ __forceinline__ void up_taps(int o, int lim, int& a, int& b, float& fa, float& fb)
{
    int i = o >> 1;
    if (o & 1) { a = i;                    b = (i + 1 < lim) ? i + 1 : lim; fa = 0.75f; fb = 0.25f; }
    else       { a = (i - 1 > 0) ? i - 1 : 0; b = i;                        fa = 0.25f; fb = 0.75f; }
}

__host__ __device__ constexpr int cpad_calc(int xr, int cw)
{
    int p = cw;
    while ((xr * p) % 32 != 8) p++;
    return p;
}

// ---------------- prep kernels ----------------
// x NCHW fp32 -> half2 pair-interleaved [n][ci2][4096]
__global__ void pack_x_kernel(const float* __restrict__ src, uint32_t* __restrict__ dst)
{
    int idx = blockIdx.x * 256 + threadIdx.x;    // 8*128*4096 total, exact
    int n   = idx >> 19;
    int rem = idx & 524287;
    int c2  = rem >> 12;
    int px  = rem & 4095;
    const float* S = src + ((size_t)n * 256 + 2 * c2) * 4096 + px;
    dst[idx] = pack_h2(S[0], S[4096]);
}

// w [cout][256][3][3] -> [ci2][tap][co] half2, scaled
__global__ void w3_pack_kernel(const float* __restrict__ w, uint32_t* __restrict__ wt,
                               int cout, float scale)
{
    int idx = blockIdx.x * 256 + threadIdx.x;
    if (idx >= 128 * 9 * cout) return;
    int c2  = idx / (9 * cout);
    int rem = idx - c2 * 9 * cout;
    int tap = rem / cout;
    int co  = rem - tap * cout;
    float lo = w[((size_t)co * 256 + 2 * c2) * 9 + tap] * scale;
    float hi = w[((size_t)co * 256 + 2 * c2 + 1) * 9 + tap] * scale;
    wt[idx] = pack_h2(lo, hi);
}

// wsk [128][256] -> [ci2][co] half2, scaled
__global__ void w1x1_pack_kernel(const float* __restrict__ w, uint32_t* __restrict__ wt,
                                 float scale)
{
    int idx = blockIdx.x * 256 + threadIdx.x;    // 16384 exact
    int c2 = idx >> 7;
    int co = idx & 127;
    wt[idx] = pack_h2(w[co * 256 + 2 * c2] * scale, w[co * 256 + 2 * c2 + 1] * scale);
}

// bilinear 2x upsample fp32 NCHW -> half2 pair-interleaved [n][ci2][16384]
__global__ void upsample2x_pack_kernel(const float* __restrict__ src, uint32_t* __restrict__ dst)
{
    int idx = blockIdx.x * 256 + threadIdx.x;    // 8*128*16384 total, exact
    int n   = idx >> 21;
    int rem = idx & 2097151;
    int c2  = rem >> 14;
    int oh  = (rem >> 7) & 127;
    int ow  = rem & 127;
    int ha, hb, wa, wb; float fha, fhb, fwa, fwb;
    up_taps(oh, 63, ha, hb, fha, fhb);
    up_taps(ow, 63, wa, wb, fwa, fwb);
    const float* S0 = src + ((size_t)n * 256 + 2 * c2) * 4096;
    const float* S1 = S0 + 4096;
    float v0 = fha * (fwa * S0[ha * 64 + wa] + fwb * S0[ha * 64 + wb]) +
               fhb * (fwa * S0[hb * 64 + wa] + fwb * S0[hb * 64 + wb]);
    float v1 = fha * (fwa * S1[ha * 64 + wa] + fwb * S1[ha * 64 + wb]) +
               fhb * (fwa * S1[hb * 64 + wa] + fwb * S1[hb * 64 + wb]);
    dst[idx] = pack_h2(v0, v1);
}

// ---------------- fp16 mma implicit-GEMM conv, cp.async 2-stage pipeline ----------------
// Block: 256 thr (8 warps). Output tile: 256 px (4 rows x 64 cols) x 64 co.
// Warp: row (warp&3), co half (warp>>2); warp tile 64 px x 32 co = 4x4 m16n8k16 frags.
// Elements are half2 (ci pair) -> K=16 ci per mma, chunk = 8 pairs = 16 ci.
template <int H, int W, int KS, int COUT, bool ACT, bool FUSE>
__global__ __launch_bounds__(256, 2)
void conv_mma_kernel(const uint32_t* __restrict__ in, const uint32_t* __restrict__ wt,
                     const float* __restrict__ bias, const float* __restrict__ skip64,
                     float* __restrict__ outp)
{
    constexpr int KS2   = KS * KS;
    constexpr int PAD   = (KS == 3) ? 1 : 0;
    constexpr int TH    = 4;
    constexpr int XR    = TH + KS - 1;
    constexpr int CW    = 64 + 2 * PAD;
    constexpr int CPAD  = cpad_calc(XR, CW);
    constexpr int XRC   = XR * CPAD;          // per-ci2 stride, == 8 mod 32
    constexpr int WST   = 72;                 // per-(tap,ci2) stride, == 8 mod 32
    constexpr int WSTG  = KS2 * 8 * WST;
    constexpr int XSTG  = 8 * XRC;
    constexpr int STAGE = WSTG + XSTG;
    constexpr int NCH   = CIN2 / 8;           // 16 chunks of 8 ci-pairs

    extern __shared__ uint32_t smemu[];

    const int tid   = threadIdx.x;
    const int lane  = tid & 31;
    const int warp  = tid >> 5;
    const int g     = lane >> 2;
    const int t     = lane & 3;
    const int warpM = warp & 3;
    const int warpN = warp >> 2;

    const int n       = blockIdx.z;
    const int coBase  = blockIdx.y * 64;
    constexpr int tilesX = W / 64;
    const int colBase = (blockIdx.x % tilesX) * 64;
    const int rowBase = (blockIdx.x / tilesX) * TH;

    const uint32_t* inN = in + (size_t)n * CIN2 * H * W;

    auto stage = [&](int chunk) {
        uint32_t* base = smemu + (chunk & 1) * STAGE;
        uint32_t* Wsb  = base;
        uint32_t* Xsb  = base + WSTG;
        const int c2B = chunk * 8;
#pragma unroll
        for (int idx = tid; idx < KS2 * 8 * 16; idx += 256) {
            int q   = idx & 15;
            int c2  = (idx >> 4) & 7;
            int tap = idx >> 7;
            cp_async16(&Wsb[(tap * 8 + c2) * WST + q * 4],
                       &wt[((size_t)(c2B + c2) * KS2 + tap) * COUT + coBase + q * 4]);
        }
#pragma unroll
        for (int idx = tid; idx < 8 * XR * CW; idx += 256) {
            int c2  = idx / (XR * CW);
            int rem = idx - c2 * (XR * CW);
            int rr  = rem / CW;
            int cc  = rem - rr * CW;
            int gy  = rowBase + rr - PAD;
            int gx  = colBase + cc - PAD;
            bool ok = ((unsigned)gy < (unsigned)H) && ((unsigned)gx < (unsigned)W);
            const uint32_t* src = ok ? &inN[(size_t)(c2B + c2) * H * W + gy * W + gx] : inN;
            cp_async4_z(&Xsb[c2 * XRC + rr * CPAD + cc], src, ok);
        }
    };

    float acc[4][4][4];
#pragma unroll
    for (int i = 0; i < 4; i++)
#pragma unroll
        for (int j = 0; j < 4; j++)
#pragma unroll
            for (int k = 0; k < 4; k++) acc[i][j][k] = 0.f;

    stage(0); cp_commit();
    stage(1); cp_commit();

    for (int c = 0; c < NCH; c++) {
        if (c + 1 < NCH) cp_wait<1>(); else cp_wait<0>();
        __syncthreads();

        const uint32_t* base = smemu + (c & 1) * STAGE;
        const uint32_t* Wsb  = base;
        const uint32_t* Xsb  = base + WSTG;

#pragma unroll
        for (int ky = 0; ky < KS; ky++)
#pragma unroll
            for (int kx = 0; kx < KS; kx++) {
                const int tap = ky * KS + kx;
                uint32_t a[4][4], b[4][2];
#pragma unroll
                for (int mf = 0; mf < 4; mf++) {
                    const int cb = mf * 16 + g;
                    const uint32_t* p = &Xsb[(warpM + ky) * CPAD + cb + kx];
                    a[mf][0] = p[t * XRC];          // px g,    k 2t..2t+1
                    a[mf][1] = p[t * XRC + 8];      // px g+8
                    a[mf][2] = p[(t + 4) * XRC];    // px g,    k 2t+8..
                    a[mf][3] = p[(t + 4) * XRC + 8];
                }
#pragma unroll
                for (int nf = 0; nf < 4; nf++) {
                    const int co = warpN * 32 + nf * 8 + g;
                    b[nf][0] = Wsb[(tap * 8 + t) * WST + co];
                    b[nf][1] = Wsb[(tap * 8 + t + 4) * WST + co];
                }
#pragma unroll
                for (int mf = 0; mf < 4; mf++)
#pragma unroll
                    for (int nf = 0; nf < 4; nf++)
                        mma_f16(acc[mf][nf], a[mf], b[nf]);
            }
        __syncthreads();

        if (c + 2 < NCH) { stage(c + 2); cp_commit(); }
    }

    // ---- epilogue: bias + leaky*sqrt2 [+ inline bilinear skip add, /sqrt2] ----
    const int gy = rowBase + warpM;
    int ha = 0, hb = 0; float fha = 0.f, fhb = 0.f;
    if (FUSE) up_taps(gy, 63, ha, hb, fha, fhb);

#pragma unroll
    for (int nf = 0; nf < 4; nf++) {
#pragma unroll
        for (int q = 0; q < 2; q++) {
            const int co = coBase + warpN * 32 + nf * 8 + t * 2 + q;
            const float bv = ACT ? __ldg(&bias[co]) : 0.f;
            const float* S = FUSE ? (skip64 + ((size_t)n * 128 + co) * 4096) : nullptr;
#pragma unroll
            for (int mf = 0; mf < 4; mf++) {
                const int cb = mf * 16 + g;
#pragma unroll
                for (int h = 0; h < 2; h++) {
                    const int gx = colBase + cb + h * 8;
                    float v = acc[mf][nf][h * 2 + q] + bv;
                    if (ACT) v *= (v >= 0.f) ? SQRT2F : (0.2f * SQRT2F);
                    size_t oidx = (((size_t)n * COUT + co) * H + gy) * W + gx;
                    if (FUSE) {
                        int wa, wb; float fwa, fwb;
                        up_taps(gx, 63, wa, wb, fwa, fwb);
                        float sk = fha * (fwa * S[ha * 64 + wa] + fwb * S[ha * 64 + wb]) +
                                   fhb * (fwa * S[hb * 64 + wa] + fwb * S[hb * 64 + wb]);
                        v = (v + sk) * INV_SQRT2F;
                    }
                    outp[oidx] = v;
                }
            }
        }
    }
}

// ---------------- launch ----------------
extern "C" void kernel_launch(void* const* d_in, const int* in_sizes, int n_in,
                              void* d_out, int out_size)
{
    const float* x   = (const float*)d_in[0];
    const float* w1  = (const float*)d_in[1];
    const float* b1  = (const float*)d_in[2];
    const float* w2  = (const float*)d_in[3];
    const float* b2  = (const float*)d_in[4];
    const float* wsk = (const float*)d_in[5];
    float* out = (float*)d_out;

    void *p0, *p1, *p2, *p3, *p4, *p5, *p6;
    cudaGetSymbolAddress(&p0, g_tmp1);
    cudaGetSymbolAddress(&p1, g_uph);
    cudaGetSymbolAddress(&p2, g_skip);
    cudaGetSymbolAddress(&p3, g_xh);
    cudaGetSymbolAddress(&p4, g_w1t);
    cudaGetSymbolAddress(&p5, g_w2t);
    cudaGetSymbolAddress(&p6, g_wskt);
    float*    tmp1 = (float*)p0;
    uint32_t* uph  = (uint32_t*)p1;
    float*    skip = (float*)p2;
    uint32_t* xh   = (uint32_t*)p3;
    uint32_t* w1t  = (uint32_t*)p4;
    uint32_t* w2t  = (uint32_t*)p5;
    uint32_t* wskt = (uint32_t*)p6;

    const float scale3 = 1.0f / 48.0f;   // 1/sqrt(256*9)
    const float scale1 = 1.0f / 16.0f;   // 1/sqrt(256)

    auto kconv1 = conv_mma_kernel<64, 64, 3, 256, true, false>;
    auto kconv2 = conv_mma_kernel<128, 128, 3, 128, true, true>;
    auto kskip  = conv_mma_kernel<64, 64, 1, 128, false, false>;

    constexpr int SM_CV = 2 * (9 * 8 * 72 + 8 * 6 * cpad_calc(6, 66)) * 4;  // 70656
    constexpr int SM_SK = 2 * (1 * 8 * 72 + 8 * 4 * cpad_calc(4, 64)) * 4;  // 21504

    cudaFuncSetAttribute(kconv1, cudaFuncAttributeMaxDynamicSharedMemorySize, SM_CV);
    cudaFuncSetAttribute(kconv2, cudaFuncAttributeMaxDynamicSharedMemorySize, SM_CV);
    cudaFuncSetAttribute(kskip,  cudaFuncAttributeMaxDynamicSharedMemorySize, SM_SK);

    // prep: pack x + weights to half2 pair-interleaved
    pack_x_kernel<<<16384, 256>>>(x, xh);
    w3_pack_kernel<<<1152, 256>>>(w1, w1t, 256, scale3);
    w3_pack_kernel<<<576, 256>>>(w2, w2t, 128, scale3);
    w1x1_pack_kernel<<<64, 256>>>(wsk, wskt, scale1);

    // skip: 1x1 conv at 64x64 (commuted past upsample); upsampled inline in conv2 epilogue
    kskip<<<dim3(16, 2, 8), 256, SM_SK>>>(xh, wskt, nullptr, nullptr, skip);

    // conv1 + FusedLeakyReLU at 64x64 (fp32 out)
    kconv1<<<dim3(16, 4, 8), 256, SM_CV>>>(xh, w1t, b1, nullptr, tmp1);

    // bilinear 2x upsample of activations -> half2 pairs for conv2
    upsample2x_pack_kernel<<<65536, 256>>>(tmp1, uph);

    // conv2 + FusedLeakyReLU at 128^2, fused bilinear-skip add + /sqrt(2)
    kconv2<<<dim3(64, 2, 8), 256, SM_CV>>>(uph, w2t, b2, skip, out);
}

// round 9
// speedup vs baseline: 10.0741x; 1.0025x over previous
#include <cuda_runtime.h>
#include <cuda_fp16.h>
#include <cstdint>

#define CIN2 128   // channel pairs
#define SQRT2F 1.41421356237309515f
#define INV_SQRT2F 0.70710678118654752f

// ---------------- scratch (device globals: no cudaMalloc allowed) ----------------
__device__ uint32_t g_xh  [8u * 128u * 64u * 64u];    // x, half2 ci-pair interleaved
__device__ float    g_tmp1[8u * 256u * 64u * 64u];    // conv1 out (post-act, fp32 NCHW)
__device__ uint32_t g_uph [8u * 128u * 128u * 128u];  // upsampled conv1 out, half2 pairs
__device__ float    g_skip[8u * 128u * 64u * 64u];    // 1x1 skip at 64x64 (fp32)
__device__ uint32_t g_w1t [128u * 9u * 256u];         // [ci2][tap][co] half2, scaled
__device__ uint32_t g_w2t [128u * 9u * 128u];
__device__ uint32_t g_wskt[128u * 128u];              // [ci2][co] half2

// ---------------- small helpers ----------------
__device__ __forceinline__ uint32_t pack_h2(float lo, float hi)
{
    __half2 h = __floats2half2_rn(lo, hi);
    return *reinterpret_cast<uint32_t*>(&h);
}

__device__ __forceinline__ void mma_f16(float* c, const uint32_t* a, const uint32_t* b)
{
    asm volatile(
        "mma.sync.aligned.m16n8k16.row.col.f32.f16.f16.f32 "
        "{%0,%1,%2,%3}, {%4,%5,%6,%7}, {%8,%9}, {%0,%1,%2,%3};"
        : "+f"(c[0]), "+f"(c[1]), "+f"(c[2]), "+f"(c[3])
        : "r"(a[0]), "r"(a[1]), "r"(a[2]), "r"(a[3]), "r"(b[0]), "r"(b[1]));
}

__device__ __forceinline__ void cp_async4_z(void* dst, const void* src, bool ok)
{
    uint32_t d = (uint32_t)__cvta_generic_to_shared(dst);
    int sz = ok ? 4 : 0;
    asm volatile("cp.async.ca.shared.global [%0], [%1], 4, %2;" :: "r"(d), "l"(src), "r"(sz));
}
__device__ __forceinline__ void cp_async16(void* dst, const void* src)
{
    uint32_t d = (uint32_t)__cvta_generic_to_shared(dst);
    asm volatile("cp.async.cg.shared.global [%0], [%1], 16;" :: "r"(d), "l"(src));
}
__device__ __forceinline__ void cp_commit() { asm volatile("cp.async.commit_group;"); }
template <int N>
__device__ __forceinline__ void cp_wait() { asm volatile("cp.async.wait_group %0;" :: "n"(N)); }

__device__ __forceinline__ void up_taps(int o, int lim, int& a, int& b, float& fa, float& fb)
{
    int i = o >> 1;
    if (o & 1) { a = i;                    b = (i + 1 < lim) ? i + 1 : lim; fa = 0.75f; fb = 0.25f; }
    else       { a = (i - 1 > 0) ? i - 1 : 0; b = i;                        fa = 0.25f; fb = 0.75f; }
}

__host__ __device__ constexpr int cpad_calc(int xr, int cw)
{
    int p = cw;
    while ((xr * p) % 32 != 8) p++;
    return p;
}

// ---------------- prep kernels ----------------
// x NCHW fp32 -> half2 pair-interleaved [n][ci2][4096]
__global__ void pack_x_kernel(const float* __restrict__ src, uint32_t* __restrict__ dst)
{
    int idx = blockIdx.x * 256 + threadIdx.x;    // 8*128*4096 total, exact
    int n   = idx >> 19;
    int rem = idx & 524287;
    int c2  = rem >> 12;
    int px  = rem & 4095;
    const float* S = src + ((size_t)n * 256 + 2 * c2) * 4096 + px;
    dst[idx] = pack_h2(S[0], S[4096]);
}

// w [cout][256][3][3] -> [ci2][tap][co] half2, scaled
__global__ void w3_pack_kernel(const float* __restrict__ w, uint32_t* __restrict__ wt,
                               int cout, float scale)
{
    int idx = blockIdx.x * 256 + threadIdx.x;
    if (idx >= 128 * 9 * cout) return;
    int c2  = idx / (9 * cout);
    int rem = idx - c2 * 9 * cout;
    int tap = rem / cout;
    int co  = rem - tap * cout;
    float lo = w[((size_t)co * 256 + 2 * c2) * 9 + tap] * scale;
    float hi = w[((size_t)co * 256 + 2 * c2 + 1) * 9 + tap] * scale;
    wt[idx] = pack_h2(lo, hi);
}

// wsk [128][256] -> [ci2][co] half2, scaled
__global__ void w1x1_pack_kernel(const float* __restrict__ w, uint32_t* __restrict__ wt,
                                 float scale)
{
    int idx = blockIdx.x * 256 + threadIdx.x;    // 16384 exact
    int c2 = idx >> 7;
    int co = idx & 127;
    wt[idx] = pack_h2(w[co * 256 + 2 * c2] * scale, w[co * 256 + 2 * c2 + 1] * scale);
}

// bilinear 2x upsample fp32 NCHW -> half2 pair-interleaved [n][ci2][16384]
__global__ void upsample2x_pack_kernel(const float* __restrict__ src, uint32_t* __restrict__ dst)
{
    int idx = blockIdx.x * 256 + threadIdx.x;    // 8*128*16384 total, exact
    int n   = idx >> 21;
    int rem = idx & 2097151;
    int c2  = rem >> 14;
    int oh  = (rem >> 7) & 127;
    int ow  = rem & 127;
    int ha, hb, wa, wb; float fha, fhb, fwa, fwb;
    up_taps(oh, 63, ha, hb, fha, fhb);
    up_taps(ow, 63, wa, wb, fwa, fwb);
    const float* S0 = src + ((size_t)n * 256 + 2 * c2) * 4096;
    const float* S1 = S0 + 4096;
    float v0 = fha * (fwa * S0[ha * 64 + wa] + fwb * S0[ha * 64 + wb]) +
               fhb * (fwa * S0[hb * 64 + wa] + fwb * S0[hb * 64 + wb]);
    float v1 = fha * (fwa * S1[ha * 64 + wa] + fwb * S1[ha * 64 + wb]) +
               fhb * (fwa * S1[hb * 64 + wa] + fwb * S1[hb * 64 + wb]);
    dst[idx] = pack_h2(v0, v1);
}

// ---------------- fp16 mma implicit-GEMM conv, cp.async 2-stage pipeline ----------------
// Block: 256 thr (8 warps). Output tile: 256 px (4 rows x 64 cols) x 64 co.
// Warp: row (warp&3), co half (warp>>2); warp tile 64 px x 32 co = 4x4 m16n8k16 frags.
// Elements are half2 (ci pair) -> K=16 ci per mma, chunk = 8 pairs = 16 ci.
template <int H, int W, int KS, int COUT, bool ACT, bool FUSE>
__global__ __launch_bounds__(256, 2)
void conv_mma_kernel(const uint32_t* __restrict__ in, const uint32_t* __restrict__ wt,
                     const float* __restrict__ bias, const float* __restrict__ skip64,
                     float* __restrict__ outp)
{
    constexpr int KS2   = KS * KS;
    constexpr int PAD   = (KS == 3) ? 1 : 0;
    constexpr int TH    = 4;
    constexpr int XR    = TH + KS - 1;
    constexpr int CW    = 64 + 2 * PAD;
    constexpr int CPAD  = cpad_calc(XR, CW);
    constexpr int XRC   = XR * CPAD;          // per-ci2 stride, == 8 mod 32
    constexpr int WST   = 72;                 // per-(tap,ci2) stride, == 8 mod 32
    constexpr int WSTG  = KS2 * 8 * WST;
    constexpr int XSTG  = 8 * XRC;
    constexpr int STAGE = WSTG + XSTG;
    constexpr int NCH   = CIN2 / 8;           // 16 chunks of 8 ci-pairs

    extern __shared__ uint32_t smemu[];

    const int tid   = threadIdx.x;
    const int lane  = tid & 31;
    const int warp  = tid >> 5;
    const int g     = lane >> 2;
    const int t     = lane & 3;
    const int warpM = warp & 3;
    const int warpN = warp >> 2;

    const int n       = blockIdx.z;
    const int coBase  = blockIdx.y * 64;
    constexpr int tilesX = W / 64;
    const int colBase = (blockIdx.x % tilesX) * 64;
    const int rowBase = (blockIdx.x / tilesX) * TH;

    const uint32_t* inN = in + (size_t)n * CIN2 * H * W;

    auto stage = [&](int chunk) {
        uint32_t* base = smemu + (chunk & 1) * STAGE;
        uint32_t* Wsb  = base;
        uint32_t* Xsb  = base + WSTG;
        const int c2B = chunk * 8;
#pragma unroll
        for (int idx = tid; idx < KS2 * 8 * 16; idx += 256) {
            int q   = idx & 15;
            int c2  = (idx >> 4) & 7;
            int tap = idx >> 7;
            cp_async16(&Wsb[(tap * 8 + c2) * WST + q * 4],
                       &wt[((size_t)(c2B + c2) * KS2 + tap) * COUT + coBase + q * 4]);
        }
#pragma unroll
        for (int idx = tid; idx < 8 * XR * CW; idx += 256) {
            int c2  = idx / (XR * CW);
            int rem = idx - c2 * (XR * CW);
            int rr  = rem / CW;
            int cc  = rem - rr * CW;
            int gy  = rowBase + rr - PAD;
            int gx  = colBase + cc - PAD;
            bool ok = ((unsigned)gy < (unsigned)H) && ((unsigned)gx < (unsigned)W);
            const uint32_t* src = ok ? &inN[(size_t)(c2B + c2) * H * W + gy * W + gx] : inN;
            cp_async4_z(&Xsb[c2 * XRC + rr * CPAD + cc], src, ok);
        }
    };

    float acc[4][4][4];
#pragma unroll
    for (int i = 0; i < 4; i++)
#pragma unroll
        for (int j = 0; j < 4; j++)
#pragma unroll
            for (int k = 0; k < 4; k++) acc[i][j][k] = 0.f;

    stage(0); cp_commit();
    stage(1); cp_commit();

    for (int c = 0; c < NCH; c++) {
        if (c + 1 < NCH) cp_wait<1>(); else cp_wait<0>();
        __syncthreads();

        const uint32_t* base = smemu + (c & 1) * STAGE;
        const uint32_t* Wsb  = base;
        const uint32_t* Xsb  = base + WSTG;

#pragma unroll
        for (int ky = 0; ky < KS; ky++)
#pragma unroll
            for (int kx = 0; kx < KS; kx++) {
                const int tap = ky * KS + kx;
                uint32_t a[4][4], b[4][2];
#pragma unroll
                for (int mf = 0; mf < 4; mf++) {
                    const int cb = mf * 16 + g;
                    const uint32_t* p = &Xsb[(warpM + ky) * CPAD + cb + kx];
                    a[mf][0] = p[t * XRC];          // px g,    k 2t..2t+1
                    a[mf][1] = p[t * XRC + 8];      // px g+8
                    a[mf][2] = p[(t + 4) * XRC];    // px g,    k 2t+8..
                    a[mf][3] = p[(t + 4) * XRC + 8];
                }
#pragma unroll
                for (int nf = 0; nf < 4; nf++) {
                    const int co = warpN * 32 + nf * 8 + g;
                    b[nf][0] = Wsb[(tap * 8 + t) * WST + co];
                    b[nf][1] = Wsb[(tap * 8 + t + 4) * WST + co];
                }
#pragma unroll
                for (int mf = 0; mf < 4; mf++)
#pragma unroll
                    for (int nf = 0; nf < 4; nf++)
                        mma_f16(acc[mf][nf], a[mf], b[nf]);
            }
        __syncthreads();

        if (c + 2 < NCH) { stage(c + 2); cp_commit(); }
    }

    // ---- epilogue: bias + leaky*sqrt2 [+ inline bilinear skip add, /sqrt2] ----
    const int gy = rowBase + warpM;
    int ha = 0, hb = 0; float fha = 0.f, fhb = 0.f;
    if (FUSE) up_taps(gy, 63, ha, hb, fha, fhb);

#pragma unroll
    for (int nf = 0; nf < 4; nf++) {
#pragma unroll
        for (int q = 0; q < 2; q++) {
            const int co = coBase + warpN * 32 + nf * 8 + t * 2 + q;
            const float bv = ACT ? __ldg(&bias[co]) : 0.f;
            const float* S = FUSE ? (skip64 + ((size_t)n * 128 + co) * 4096) : nullptr;
#pragma unroll
            for (int mf = 0; mf < 4; mf++) {
                const int cb = mf * 16 + g;
#pragma unroll
                for (int h = 0; h < 2; h++) {
                    const int gx = colBase + cb + h * 8;
                    float v = acc[mf][nf][h * 2 + q] + bv;
                    if (ACT) v *= (v >= 0.f) ? SQRT2F : (0.2f * SQRT2F);
                    size_t oidx = (((size_t)n * COUT + co) * H + gy) * W + gx;
                    if (FUSE) {
                        int wa, wb; float fwa, fwb;
                        up_taps(gx, 63, wa, wb, fwa, fwb);
                        float sk = fha * (fwa * S[ha * 64 + wa] + fwb * S[ha * 64 + wb]) +
                                   fhb * (fwa * S[hb * 64 + wa] + fwb * S[hb * 64 + wb]);
                        v = (v + sk) * INV_SQRT2F;
                    }
                    outp[oidx] = v;
                }
            }
        }
    }
}

// ---------------- launch ----------------
extern "C" void kernel_launch(void* const* d_in, const int* in_sizes, int n_in,
                              void* d_out, int out_size)
{
    const float* x   = (const float*)d_in[0];
    const float* w1  = (const float*)d_in[1];
    const float* b1  = (const float*)d_in[2];
    const float* w2  = (const float*)d_in[3];
    const float* b2  = (const float*)d_in[4];
    const float* wsk = (const float*)d_in[5];
    float* out = (float*)d_out;

    void *p0, *p1, *p2, *p3, *p4, *p5, *p6;
    cudaGetSymbolAddress(&p0, g_tmp1);
    cudaGetSymbolAddress(&p1, g_uph);
    cudaGetSymbolAddress(&p2, g_skip);
    cudaGetSymbolAddress(&p3, g_xh);
    cudaGetSymbolAddress(&p4, g_w1t);
    cudaGetSymbolAddress(&p5, g_w2t);
    cudaGetSymbolAddress(&p6, g_wskt);
    float*    tmp1 = (float*)p0;
    uint32_t* uph  = (uint32_t*)p1;
    float*    skip = (float*)p2;
    uint32_t* xh   = (uint32_t*)p3;
    uint32_t* w1t  = (uint32_t*)p4;
    uint32_t* w2t  = (uint32_t*)p5;
    uint32_t* wskt = (uint32_t*)p6;

    const float scale3 = 1.0f / 48.0f;   // 1/sqrt(256*9)
    const float scale1 = 1.0f / 16.0f;   // 1/sqrt(256)

    auto kconv1 = conv_mma_kernel<64, 64, 3, 256, true, false>;
    auto kconv2 = conv_mma_kernel<128, 128, 3, 128, true, true>;
    auto kskip  = conv_mma_kernel<64, 64, 1, 128, false, false>;

    constexpr int SM_CV = 2 * (9 * 8 * 72 + 8 * 6 * cpad_calc(6, 66)) * 4;  // 70656
    constexpr int SM_SK = 2 * (1 * 8 * 72 + 8 * 4 * cpad_calc(4, 64)) * 4;  // 21504

    cudaFuncSetAttribute(kconv1, cudaFuncAttributeMaxDynamicSharedMemorySize, SM_CV);
    cudaFuncSetAttribute(kconv2, cudaFuncAttributeMaxDynamicSharedMemorySize, SM_CV);
    cudaFuncSetAttribute(kskip,  cudaFuncAttributeMaxDynamicSharedMemorySize, SM_SK);

    // prep: pack x + weights to half2 pair-interleaved
    pack_x_kernel<<<16384, 256>>>(x, xh);
    w3_pack_kernel<<<1152, 256>>>(w1, w1t, 256, scale3);
    w3_pack_kernel<<<576, 256>>>(w2, w2t, 128, scale3);
    w1x1_pack_kernel<<<64, 256>>>(wsk, wskt, scale1);

    // skip: 1x1 conv at 64x64 (commuted past upsample); upsampled inline in conv2 epilogue
    kskip<<<dim3(16, 2, 8), 256, SM_SK>>>(xh, wskt, nullptr, nullptr, skip);

    // conv1 + FusedLeakyReLU at 64x64 (fp32 out)
    kconv1<<<dim3(16, 4, 8), 256, SM_CV>>>(xh, w1t, b1, nullptr, tmp1);

    // bilinear 2x upsample of activations -> half2 pairs for conv2
    upsample2x_pack_kernel<<<65536, 256>>>(tmp1, uph);

    // conv2 + FusedLeakyReLU at 128^2, fused bilinear-skip add + /sqrt(2)
    kconv2<<<dim3(64, 2, 8), 256, SM_CV>>>(uph, w2t, b2, skip, out);
}

// round 12
// speedup vs baseline: 10.3213x; 1.0245x over previous
#include <cuda_runtime.h>
#include <cuda_fp16.h>
#include <cstdint>

#define SQRT2F 1.41421356237309515f
#define INV_SQRT2F 0.70710678118654752f

// ---------------- scratch ----------------
__device__ __align__(16) __half   g_xh  [8ull * 4096 * 256];     // x NHWC f16
__device__ __align__(16) float    g_tmp1[8ull * 256 * 64 * 64];  // conv1 out fp32 NCHW
__device__ __align__(16) __half   g_uph [8ull * 16384 * 256];    // upsampled NHWC f16
__device__ __align__(16) float    g_skip[8ull * 128 * 64 * 64];  // skip 64^2 fp32 NCHW
__device__ __align__(16) uint32_t g_w1L [4ull * 16 * 9 * 768];   // padded smem-image weights
__device__ __align__(16) uint32_t g_w2L [2ull * 16 * 9 * 768];
__device__ __align__(16) uint32_t g_wskL[2ull * 16 * 1 * 768];

// ---------------- helpers ----------------
__device__ __forceinline__ uint32_t smem_u32(const void* p)
{ return (uint32_t)__cvta_generic_to_shared(p); }

__device__ __forceinline__ void mma_f16(float* c, const uint32_t* a, const uint32_t* b)
{
    asm volatile(
        "mma.sync.aligned.m16n8k16.row.col.f32.f16.f16.f32 "
        "{%0,%1,%2,%3}, {%4,%5,%6,%7}, {%8,%9}, {%0,%1,%2,%3};"
        : "+f"(c[0]), "+f"(c[1]), "+f"(c[2]), "+f"(c[3])
        : "r"(a[0]), "r"(a[1]), "r"(a[2]), "r"(a[3]), "r"(b[0]), "r"(b[1]));
}

__device__ __forceinline__ void ldsm4(uint32_t* r, uint32_t addr)
{
    asm volatile("ldmatrix.sync.aligned.m8n8.x4.shared.b16 {%0,%1,%2,%3}, [%4];"
                 : "=r"(r[0]), "=r"(r[1]), "=r"(r[2]), "=r"(r[3]) : "r"(addr));
}

__device__ __forceinline__ void cp16(void* d, const void* s)
{ asm volatile("cp.async.cg.shared.global [%0], [%1], 16;" :: "r"(smem_u32(d)), "l"(s)); }
__device__ __forceinline__ void cp16z(void* d, const void* s, bool ok)
{ int sz = ok ? 16 : 0;
  asm volatile("cp.async.cg.shared.global [%0], [%1], 16, %2;" :: "r"(smem_u32(d)), "l"(s), "r"(sz)); }
__device__ __forceinline__ void cpc() { asm volatile("cp.async.commit_group;"); }
template <int N> __device__ __forceinline__ void cpw()
{ asm volatile("cp.async.wait_group %0;" :: "n"(N)); }

__device__ __forceinline__ void up_taps(int o, int lim, int& a, int& b, float& fa, float& fb)
{
    int i = o >> 1;
    if (o & 1) { a = i; b = (i + 1 < lim) ? i + 1 : lim; fa = 0.75f; fb = 0.25f; }
    else       { a = (i - 1 > 0) ? i - 1 : 0; b = i;     fa = 0.25f; fb = 0.75f; }
}

// ---------------- prep: x NCHW fp32 -> NHWC f16 ----------------
__global__ void pack_x_nhwc(const float* __restrict__ src, __half* __restrict__ dst)
{
    __shared__ float tile[32][33];
    int n = blockIdx.z, c0 = blockIdx.y * 32, p0 = blockIdx.x * 32;
    int tx = threadIdx.x, ty = threadIdx.y;
    const float* S = src + (size_t)n * 256 * 4096;
    __half* D = dst + (size_t)n * 4096 * 256;
#pragma unroll
    for (int i = 0; i < 32; i += 8) tile[ty + i][tx] = S[(size_t)(c0 + ty + i) * 4096 + p0 + tx];
    __syncthreads();
#pragma unroll
    for (int i = 0; i < 32; i += 8)
        D[(size_t)(p0 + ty + i) * 256 + c0 + tx] = __float2half(tile[tx][ty + i]);
}

// ---------------- prep: weights -> padded co-major smem image ----------------
// dst u32 index: t2*768 + co*12 + j,  t2 = (coblk*16 + chunk)*ks2 + tap, j<8 data (16 ci)
__global__ void wL_prep(const float* __restrict__ w, uint32_t* __restrict__ dst,
                        int ks2, float scale, int total)
{
    int idx = blockIdx.x * 256 + threadIdx.x;
    if (idx >= total) return;
    int j  = idx & 7;
    int t1 = idx >> 3;
    int co = t1 & 63;
    int t2 = t1 >> 6;
    int tap   = t2 % ks2;
    int t3    = t2 / ks2;
    int chunk = t3 & 15;
    int coblk = t3 >> 4;
    int cog = coblk * 64 + co;
    int ci  = chunk * 16 + 2 * j;
    float lo = w[((size_t)cog * 256 + ci) * ks2 + tap] * scale;
    float hi = w[((size_t)cog * 256 + ci + 1) * ks2 + tap] * scale;
    __half2 h = __floats2half2_rn(lo, hi);
    dst[(size_t)t2 * 768 + co * 12 + j] = *reinterpret_cast<uint32_t*>(&h);
}

// ---------------- prep: upsample fp32 NCHW 64^2 -> NHWC f16 128^2 ----------------
__global__ void upsample_nhwc(const float* __restrict__ src, uint32_t* __restrict__ dst)
{
    __shared__ uint32_t tile[32][129];
    int n = blockIdx.z, oh = blockIdx.y, owb = blockIdx.x * 32;
    int t = threadIdx.x, tx = t & 31, wz = t >> 5;
    int ha, hb, wa, wb; float fha, fhb, fwa, fwb;
    up_taps(oh, 63, ha, hb, fha, fhb);
    up_taps(owb + tx, 63, wa, wb, fwa, fwb);
    const float* B = src + (size_t)n * 256 * 4096;
#pragma unroll 4
    for (int i = 0; i < 16; i++) {
        int c2 = wz * 16 + i;
        const float* S0 = B + (size_t)(2 * c2) * 4096;
        const float* S1 = S0 + 4096;
        float v0 = fha * (fwa * S0[ha * 64 + wa] + fwb * S0[ha * 64 + wb]) +
                   fhb * (fwa * S0[hb * 64 + wa] + fwb * S0[hb * 64 + wb]);
        float v1 = fha * (fwa * S1[ha * 64 + wa] + fwb * S1[ha * 64 + wb]) +
                   fhb * (fwa * S1[hb * 64 + wa] + fwb * S1[hb * 64 + wb]);
        __half2 h = __floats2half2_rn(v0, v1);
        tile[tx][c2] = *reinterpret_cast<uint32_t*>(&h);
    }
    __syncthreads();
    uint32_t* D = dst + ((size_t)n * 16384 + oh * 128 + owb) * 128;
    int c = t & 127, j0 = t >> 7;
#pragma unroll
    for (int k = 0; k < 16; k++) { int j = 2 * k + j0; D[(size_t)j * 128 + c] = tile[j][c]; }
}

// ---------------- f16 implicit-GEMM conv: ldmatrix + mma.sync, cp.async pipeline ----
// Block: 256 thr (8 warps). Tile: (TH rows x 64 cols) px x 64 co.
// Warp: row warp&3, co half warp>>2; warp tile 64 px x 32 co = 4x4 m16n8k16.
// Smem: X pixel-major 48B/px (16 ci f16 + 16B pad), W co-major 48B/co. ldmatrix conflict-free.
template <int TH, int W, int KS, int COUT, bool ACT, bool FUSE>
__global__ __launch_bounds__(256, 2)
void conv_lds(const __half* __restrict__ xin, const uint32_t* __restrict__ wL,
              const float* __restrict__ bias, const float* __restrict__ skip64,
              float* __restrict__ outp)
{
    constexpr int KS2   = KS * KS;
    constexpr int PAD   = (KS == 3) ? 1 : 0;
    constexpr int XR    = TH + KS - 1;
    constexpr int CW    = 64 + 2 * PAD;
    constexpr int WSTG  = KS2 * 768;          // u32
    constexpr int XSTG  = XR * CW * 12;       // u32
    constexpr int STAGE = WSTG + XSTG;
    constexpr int NCH   = 16;

    extern __shared__ uint32_t smemu[];

    const int tid = threadIdx.x, lane = tid & 31, warp = tid >> 5;
    const int warpM = warp & 3, warpN = warp >> 2;
    const int n = blockIdx.z, coBase = blockIdx.y * 64;
    constexpr int tilesX = W / 64;
    const int colBase = (blockIdx.x % tilesX) * 64;
    const int rowBase = (blockIdx.x / tilesX) * TH;

    const __half* xN = xin + (size_t)n * W * W * 256;

    // ldmatrix lane bases (u32 offsets): A rows = px, B rows = co
    const int aLane = ((lane & 7) + ((lane >> 3) & 1) * 8) * 12 + (lane >> 4) * 4;
    const int bLane = ((lane & 7) + (lane >> 4) * 8) * 12 + ((lane >> 3) & 1) * 4;

    auto stage = [&](int ch) {
        uint32_t* base = smemu + (ch & 1) * STAGE;
        uint32_t* Wsb = base;
        uint32_t* Xsb = base + WSTG;
        const uint32_t* ws = wL + ((size_t)(blockIdx.y * 16 + ch) * KS2) * 768;
#pragma unroll
        for (int i = tid; i < KS2 * 128; i += 256) {
            int c16 = i & 1, co = (i >> 1) & 63, tap = i >> 7;
            int off = tap * 768 + co * 12 + c16 * 4;
            cp16(Wsb + off, ws + off);
        }
        const int ciB = ch * 16;
#pragma unroll
        for (int i = tid; i < XR * CW * 2; i += 256) {
            int p = i >> 1, g8 = i & 1;
            int hr = p / CW, hc = p - hr * CW;
            int gy = rowBase + hr - PAD, gx = colBase + hc - PAD;
            bool ok = ((unsigned)gy < (unsigned)W) && ((unsigned)gx < (unsigned)W);
            const __half* s = ok ? xN + ((size_t)gy * W + gx) * 256 + ciB + g8 * 8 : xN;
            cp16z(Xsb + p * 12 + g8 * 4, s, ok);
        }
    };

    float acc[4][4][4];
#pragma unroll
    for (int i = 0; i < 4; i++)
#pragma unroll
        for (int j = 0; j < 4; j++)
#pragma unroll
            for (int k = 0; k < 4; k++) acc[i][j][k] = 0.f;

    stage(0); cpc();
    stage(1); cpc();

    for (int c = 0; c < NCH; c++) {
        if (c + 1 < NCH) cpw<1>(); else cpw<0>();
        __syncthreads();

        uint32_t* base = smemu + (c & 1) * STAGE;
        const uint32_t wB0 = smem_u32(base) + bLane * 4;
        const uint32_t xB0 = smem_u32(base + WSTG) + aLane * 4;

#pragma unroll
        for (int ky = 0; ky < KS; ky++)
#pragma unroll
            for (int kx = 0; kx < KS; kx++) {
                const int tap = ky * KS + kx;
                const int rowOff = ((warpM + ky) * CW + kx) * 48;
                uint32_t a[4][4], bf[4][2];
#pragma unroll
                for (int mf = 0; mf < 4; mf++)
                    ldsm4(a[mf], xB0 + rowOff + mf * 768);
#pragma unroll
                for (int np = 0; np < 2; np++) {
                    uint32_t r[4];
                    ldsm4(r, wB0 + tap * 3072 + (warpN * 32 + np * 16) * 48);
                    bf[np * 2][0] = r[0]; bf[np * 2][1] = r[1];
                    bf[np * 2 + 1][0] = r[2]; bf[np * 2 + 1][1] = r[3];
                }
#pragma unroll
                for (int mf = 0; mf < 4; mf++)
#pragma unroll
                    for (int nf = 0; nf < 4; nf++)
                        mma_f16(acc[mf][nf], a[mf], bf[nf]);
            }
        __syncthreads();

        if (c + 2 < NCH) { stage(c + 2); cpc(); }
    }

    // ---- epilogue: bias + leaky*sqrt2 [+ inline bilinear skip add, /sqrt2] ----
    const int g = lane >> 2, t = lane & 3;
    const int gy = rowBase + warpM;
    int ha = 0, hb = 0; float fha = 0.f, fhb = 0.f;
    if (FUSE) up_taps(gy, 63, ha, hb, fha, fhb);

#pragma unroll
    for (int nf = 0; nf < 4; nf++) {
#pragma unroll
        for (int q = 0; q < 2; q++) {
            const int co = coBase + warpN * 32 + nf * 8 + t * 2 + q;
            const float bv = ACT ? __ldg(&bias[co]) : 0.f;
            const float* S = FUSE ? (skip64 + ((size_t)n * 128 + co) * 4096) : nullptr;
#pragma unroll
            for (int mf = 0; mf < 4; mf++) {
                const int cb = mf * 16 + g;
#pragma unroll
                for (int h = 0; h < 2; h++) {
                    const int gx = colBase + cb + h * 8;
                    float v = acc[mf][nf][h * 2 + q] + bv;
                    if (ACT) v *= (v >= 0.f) ? SQRT2F : (0.2f * SQRT2F);
                    size_t oidx = (((size_t)n * COUT + co) * W + gy) * W + gx;
                    if (FUSE) {
                        int wa, wb; float fwa, fwb;
                        up_taps(gx, 63, wa, wb, fwa, fwb);
                        float sk = fha * (fwa * S[ha * 64 + wa] + fwb * S[ha * 64 + wb]) +
                                   fhb * (fwa * S[hb * 64 + wa] + fwb * S[hb * 64 + wb]);
                        v = (v + sk) * INV_SQRT2F;
                    }
                    outp[oidx] = v;
                }
            }
        }
    }
}

// ---------------- launch ----------------
extern "C" void kernel_launch(void* const* d_in, const int* in_sizes, int n_in,
                              void* d_out, int out_size)
{
    const float* x   = (const float*)d_in[0];
    const float* w1  = (const float*)d_in[1];
    const float* b1  = (const float*)d_in[2];
    const float* w2  = (const float*)d_in[3];
    const float* b2  = (const float*)d_in[4];
    const float* wsk = (const float*)d_in[5];
    float* out = (float*)d_out;

    void *p0, *p1, *p2, *p3, *p4, *p5, *p6;
    cudaGetSymbolAddress(&p0, g_xh);
    cudaGetSymbolAddress(&p1, g_tmp1);
    cudaGetSymbolAddress(&p2, g_uph);
    cudaGetSymbolAddress(&p3, g_skip);
    cudaGetSymbolAddress(&p4, g_w1L);
    cudaGetSymbolAddress(&p5, g_w2L);
    cudaGetSymbolAddress(&p6, g_wskL);
    __half*   xh   = (__half*)p0;
    float*    tmp1 = (float*)p1;
    __half*   uph  = (__half*)p2;
    float*    skip = (float*)p3;
    uint32_t* w1L  = (uint32_t*)p4;
    uint32_t* w2L  = (uint32_t*)p5;
    uint32_t* wskL = (uint32_t*)p6;

    auto kconv1 = conv_lds<4, 64, 3, 256, true, false>;
    auto kconv2 = conv_lds<4, 128, 3, 128, true, true>;
    auto kskip  = conv_lds<4, 64, 1, 128, false, false>;

    constexpr int SM_CV = 2 * (9 * 768 + 6 * 66 * 12) * 4;   // 93312
    constexpr int SM_SK = 2 * (1 * 768 + 4 * 64 * 12) * 4;   // 30720
    cudaFuncSetAttribute(kconv1, cudaFuncAttributeMaxDynamicSharedMemorySize, SM_CV);
    cudaFuncSetAttribute(kconv2, cudaFuncAttributeMaxDynamicSharedMemorySize, SM_CV);
    cudaFuncSetAttribute(kskip,  cudaFuncAttributeMaxDynamicSharedMemorySize, SM_SK);

    // prep
    pack_x_nhwc<<<dim3(128, 8, 8), dim3(32, 8)>>>(x, xh);
    wL_prep<<<1152, 256>>>(w1, w1L, 9, 1.0f / 48.0f, 4 * 16 * 9 * 64 * 8);
    wL_prep<<<576, 256>>>(w2, w2L, 9, 1.0f / 48.0f, 2 * 16 * 9 * 64 * 8);
    wL_prep<<<64, 256>>>(wsk, wskL, 1, 1.0f / 16.0f, 2 * 16 * 1 * 64 * 8);

    // skip 1x1 at 64^2 (upsample commuted; applied inline in conv2 epilogue)
    kskip<<<dim3(16, 2, 8), 256, SM_SK>>>(xh, wskL, nullptr, nullptr, skip);

    // conv1 + FusedLeakyReLU at 64^2 (fp32 NCHW out)
    kconv1<<<dim3(16, 4, 8), 256, SM_CV>>>(xh, w1L, b1, nullptr, tmp1);

    // bilinear 2x upsample -> NHWC f16 for conv2
    upsample_nhwc<<<dim3(4, 128, 8), 256>>>(tmp1, (uint32_t*)uph);

    // conv2 + FusedLeakyReLU at 128^2, fused bilinear-skip add + /sqrt(2)
    kconv2<<<dim3(64, 2, 8), 256, SM_CV>>>(uph, w2L, b2, skip, out);
}